// round 2
// baseline (speedup 1.0000x reference)
#include <cuda_runtime.h>
#include <math.h>
#include <float.h>

// ---------------------------------------------------------------------------
// Scattering2D (J=2, L=8, 224x224) for B=16, C=3  + global max pool + linear.
// All FFTs are mixed-radix 7*2^k implemented as: 7-point DFT per lane,
// twiddle, radix-2 DIF FFT across a group of G lanes via __shfl_xor_sync.
// Twiddles come from one table w224[t] = exp(-2*pi*i*t/224) built in fp64.
// ---------------------------------------------------------------------------

#define IMG224 (224*224)

// ---- device global scratch (allocation-free rule: static __device__) ------
__device__ float2 g_w224[224];
__device__ float  g_psi0[8*IMG224];     // j=0 Morlets @224
__device__ float  g_psi1[8*IMG224];     // j=1 Morlets @224
__device__ float  g_phi0[IMG224];       // phi @224
__device__ float  g_phi1[112*112];      // phi folded to 112
__device__ float2 g_xh[48*IMG224];      // fft2(x)
__device__ float2 g_scratch[384*IMG224];// transposed intermediates
__device__ float  g_u1[384*IMG224];     // |ifft2(xh*psi0)|
__device__ float2 g_u1h2[384*IMG224];   // fft2(u1)
__device__ float  g_feat[48*81];        // scattering features (B*C, 81)

// ---- complex helpers -------------------------------------------------------
__device__ __forceinline__ float2 cmul(float2 a, float2 b){
    return make_float2(fmaf(a.x,b.x,-a.y*b.y), fmaf(a.x,b.y, a.y*b.x));
}
__device__ __forceinline__ float2 cfma(float2 a, float2 b, float2 c){
    float2 r;
    r.x = fmaf(a.x, b.x, fmaf(-a.y, b.y, c.x));
    r.y = fmaf(a.x, b.y, fmaf( a.y, b.x, c.y));
    return r;
}
template<bool INV>
__device__ __forceinline__ float2 twid(int t){
    float2 w = g_w224[t];
    if (INV) w.y = -w.y;
    return w;
}

// ---- core line FFT on 7 register values per lane ---------------------------
// Input : a[n1] = x[G*n1 + glane], n1 = 0..6 (G = 1<<LOGG lanes per line)
// Output: a[k1] = X[k1 + 7*bitrev(glane)]      (scaled by 1/N when INV)
template<int LOGG, bool INV>
__device__ __forceinline__ void fft_regs(float2 a[7], int gl){
    const int G  = 1 << LOGG;
    const int N  = 7 * G;
    const int ST = 224 / N;          // table step for lane twiddle

    float2 w7[7];
    #pragma unroll
    for (int m = 0; m < 7; m++) w7[m] = twid<INV>(32*m);

    float2 A[7];
    #pragma unroll
    for (int k1 = 0; k1 < 7; k1++){
        float2 s = a[0];
        #pragma unroll
        for (int n1 = 1; n1 < 7; n1++) s = cfma(a[n1], w7[(n1*k1) % 7], s);
        A[k1] = s;
    }
    #pragma unroll
    for (int k1 = 1; k1 < 7; k1++)
        A[k1] = cmul(A[k1], twid<INV>(gl * k1 * ST));

    #pragma unroll
    for (int m = G/2; m >= 1; m >>= 1){
        const int tstep = 224 / (2*m);
        float2 w = twid<INV>((gl & (m-1)) * tstep);
        bool up = (gl & m) != 0;
        #pragma unroll
        for (int k1 = 0; k1 < 7; k1++){
            float2 mine = A[k1];
            float2 oth;
            oth.x = __shfl_xor_sync(0xffffffffu, mine.x, m, 32);
            oth.y = __shfl_xor_sync(0xffffffffu, mine.y, m, 32);
            if (up) A[k1] = cmul(make_float2(oth.x - mine.x, oth.y - mine.y), w);
            else    A[k1] = make_float2(mine.x + oth.x, mine.y + oth.y);
        }
    }
    if (INV){
        const float s = 1.0f / (float)N;
        #pragma unroll
        for (int k1 = 0; k1 < 7; k1++){ A[k1].x *= s; A[k1].y *= s; }
    }
    #pragma unroll
    for (int k1 = 0; k1 < 7; k1++) a[k1] = A[k1];
}

// In-place FFT of one line living in shared memory.
template<int LOGG, bool INV>
__device__ __forceinline__ void fft_line(float2* buf, int stride, int gl){
    const int G = 1 << LOGG;
    float2 a[7];
    #pragma unroll
    for (int n1 = 0; n1 < 7; n1++) a[n1] = buf[(n1*G + gl)*stride];
    fft_regs<LOGG, INV>(a, gl);
    int k2 = __brev((unsigned)gl) >> (32 - LOGG);
    #pragma unroll
    for (int k1 = 0; k1 < 7; k1++) buf[(k1 + 7*k2)*stride] = a[k1];
}

// ---- in-block 2D FFTs (block = 224 threads) --------------------------------
template<bool INV>
__device__ __forceinline__ void fft2_112(float2* img){   // pitch 113
    int gl = threadIdx.x & 15, grp = threadIdx.x >> 4;   // 14 groups of 16
    for (int r = grp; r < 112; r += 14) fft_line<4, INV>(img + r*113, 1, gl);
    __syncthreads();
    for (int c = grp; c < 112; c += 14) fft_line<4, INV>(img + c, 113, gl);
    __syncthreads();
}
template<bool INV>
__device__ __forceinline__ void fft2_56(float2* img){    // pitch 57
    int gl = threadIdx.x & 7, grp = threadIdx.x >> 3;    // 28 groups of 8
    for (int r = grp; r < 56; r += 28) fft_line<3, INV>(img + r*57, 1, gl);
    __syncthreads();
    for (int c = grp; c < 56; c += 28) fft_line<3, INV>(img + c, 57, gl);
    __syncthreads();
}

__device__ __forceinline__ float blockMax224(float v){
    #pragma unroll
    for (int o = 16; o; o >>= 1) v = fmaxf(v, __shfl_xor_sync(0xffffffffu, v, o));
    __shared__ float red[7];
    int w = threadIdx.x >> 5;
    if ((threadIdx.x & 31) == 0) red[w] = v;
    __syncthreads();
    float m = -FLT_MAX;
    if (threadIdx.x == 0){
        m = red[0];
        #pragma unroll
        for (int i = 1; i < 7; i++) m = fmaxf(m, red[i]);
    }
    return m;
}

// ---- filter + twiddle generation (fp64, deterministic, every call) ---------
__device__ __forceinline__ double dfreq(int a){
    const double PI = 3.14159265358979323846;
    return 2.0*PI*(double)((a < 112) ? a : a - 224) / 224.0;
}
__global__ void gen_filters_k(){
    int t = blockIdx.x*256 + threadIdx.x;
    const double PI = 3.14159265358979323846;
    if (t < 224){
        double ang = -2.0*PI*(double)t/224.0;
        g_w224[t] = make_float2((float)cos(ang), (float)sin(ang));
        return;
    }
    int u = t - 224;
    if (u < 2*8*IMG224){
        int j = u / (8*IMG224); int r = u - j*(8*IMG224);
        int l = r / IMG224;     int e = r - l*IMG224;
        int aa = e / 224, bb = e - aa*224;
        double wx = dfreq(aa), wy = dfreq(bb);
        double th = (double)l * PI / 8.0;
        double xi = (3.0*PI/4.0) / (double)(1 << j);
        double sg = 0.8 * (double)(1 << j);
        double ct = cos(th), st = sin(th);
        double uu =  ct*wx + st*wy;
        double vv = -st*wx + ct*wy;
        double vs = vv / 0.5;                 // slant = 4/L = 0.5
        double s2 = 0.5*sg*sg;
        double gab = exp(-s2*((uu-xi)*(uu-xi) + vs*vs));
        double gau = exp(-s2*(uu*uu + vs*vs));
        double kap = exp(-s2*xi*xi);
        float val = (float)(gab - kap*gau);
        if (j == 0) g_psi0[l*IMG224 + e] = val;
        else        g_psi1[l*IMG224 + e] = val;
        return;
    }
    u -= 2*8*IMG224;
    if (u < IMG224){
        int aa = u/224, bb = u - aa*224;
        double wx = dfreq(aa), wy = dfreq(bb);
        double s2 = 0.5*1.6*1.6;
        g_phi0[u] = (float)exp(-s2*(wx*wx + wy*wy));
        return;
    }
    u -= IMG224;
    if (u < 112*112){
        int aa = u/112, bb = u - aa*112;
        double s2 = 0.5*1.6*1.6, s = 0.0;
        #pragma unroll
        for (int p = 0; p < 2; p++)
            #pragma unroll
            for (int q = 0; q < 2; q++){
                double wx = dfreq(aa + 112*p), wy = dfreq(bb + 112*q);
                s += exp(-s2*(wx*wx + wy*wy));
            }
        g_phi1[u] = (float)(s*0.25);
    }
}

// ---- @224 pass: row FFT + transposed write (pass(X) = F * X^T) -------------
// MODE 0: x(real)           -> scratch        (fwd)   [48 imgs]
// MODE 1: scratch           -> xh             (fwd)   [48]
// MODE 2: xh[i/8]*psi0[i%8] -> scratch        (inv)   [384]
// MODE 3: scratch           -> u1 (|.|, real) (inv)   [384]
// MODE 4: u1(real)          -> scratch        (fwd)   [384]
// MODE 5: scratch           -> u1h2           (fwd)   [384]
template<int MODE>
__global__ void __launch_bounds__(224) pass224_k(const float* __restrict__ xin){
    constexpr bool IN_REAL  = (MODE == 0 || MODE == 4);
    constexpr bool MUL_FILT = (MODE == 2);
    constexpr bool INV      = (MODE == 2 || MODE == 3);
    constexpr bool OUT_ABS  = (MODE == 3);

    __shared__ float2 sbuf[7][225];
    int i    = blockIdx.y;
    int w    = threadIdx.x >> 5, lane = threadIdx.x & 31;
    int row  = blockIdx.x*7 + w;

    const float2* inC = nullptr; const float* inR = nullptr; const float* filt = nullptr;
    if constexpr (MODE == 0) inR = xin + i*IMG224;
    if constexpr (MODE == 1) inC = g_scratch + i*IMG224;
    if constexpr (MODE == 2){ inC = g_xh + (i >> 3)*IMG224; filt = g_psi0 + (i & 7)*IMG224; }
    if constexpr (MODE == 3) inC = g_scratch + i*IMG224;
    if constexpr (MODE == 4) inR = g_u1 + i*IMG224;
    if constexpr (MODE == 5) inC = g_scratch + i*IMG224;

    float2 a[7];
    #pragma unroll
    for (int n1 = 0; n1 < 7; n1++){
        int idx = row*224 + n1*32 + lane;
        float2 v;
        if constexpr (IN_REAL) v = make_float2(inR[idx], 0.f);
        else                   v = inC[idx];
        if constexpr (MUL_FILT){ float f = filt[idx]; v.x *= f; v.y *= f; }
        a[n1] = v;
    }
    fft_regs<5, INV>(a, lane);
    int k2 = __brev((unsigned)lane) >> 27;
    #pragma unroll
    for (int k1 = 0; k1 < 7; k1++) sbuf[w][k1 + 7*k2] = a[k1];
    __syncthreads();

    int rr    = threadIdx.x % 7;
    int kbase = threadIdx.x / 7;
    int grow  = blockIdx.x*7 + rr;
    #pragma unroll
    for (int it = 0; it < 7; it++){
        int k = kbase + it*32;
        float2 v = sbuf[rr][k];
        if constexpr (OUT_ABS){
            g_u1[i*IMG224 + k*224 + grow] = sqrtf(v.x*v.x + v.y*v.y);
        } else {
            float2* o = (MODE == 1) ? g_xh : ((MODE == 5) ? g_u1h2 : g_scratch);
            o[i*IMG224 + k*224 + grow] = v;
        }
    }
}

// ---- fused @112 chain: fold2(src*psi) -> ifft2 -> abs -> fft2 -> *phi1
//      fold2 -> ifft2@56 -> real -> max ---------------------------------------
__device__ __forceinline__ void chain112(const float2* __restrict__ src,
                                         const float* __restrict__ psi,
                                         float* featOut){
    extern __shared__ float2 sm[];
    float2* img  = sm;             // 112 x 113
    float2* im56 = sm + 112*113;   // 56 x 57
    int tid = threadIdx.x;

    for (int e = tid; e < 112*112; e += 224){
        int aa = e/112, bb = e - aa*112;
        float2 acc = make_float2(0.f, 0.f);
        #pragma unroll
        for (int p = 0; p < 2; p++)
            #pragma unroll
            for (int q = 0; q < 2; q++){
                int idx = (aa + 112*p)*224 + (bb + 112*q);
                float f = psi[idx]; float2 uv = src[idx];
                acc.x = fmaf(uv.x, f, acc.x);
                acc.y = fmaf(uv.y, f, acc.y);
            }
        img[aa*113 + bb] = make_float2(acc.x*0.25f, acc.y*0.25f);
    }
    __syncthreads();
    fft2_112<true>(img);
    for (int e = tid; e < 112*112; e += 224){
        int aa = e/112, bb = e - aa*112;
        float2 z = img[aa*113 + bb];
        img[aa*113 + bb] = make_float2(sqrtf(z.x*z.x + z.y*z.y), 0.f);
    }
    __syncthreads();
    fft2_112<false>(img);
    for (int e = tid; e < 56*56; e += 224){
        int aa = e/56, bb = e - aa*56;
        float2 acc = make_float2(0.f, 0.f);
        #pragma unroll
        for (int p = 0; p < 2; p++)
            #pragma unroll
            for (int q = 0; q < 2; q++){
                int ia = aa + 56*p, ib = bb + 56*q;
                float f = g_phi1[ia*112 + ib]; float2 uv = img[ia*113 + ib];
                acc.x = fmaf(uv.x, f, acc.x);
                acc.y = fmaf(uv.y, f, acc.y);
            }
        im56[aa*57 + bb] = make_float2(acc.x*0.25f, acc.y*0.25f);
    }
    __syncthreads();
    fft2_56<true>(im56);
    float mx = -FLT_MAX;
    for (int e = tid; e < 56*56; e += 224){
        int aa = e/56, bb = e - aa*56;
        mx = fmaxf(mx, im56[aa*57 + bb].x);
    }
    float m = blockMax224(mx);
    if (tid == 0) *featOut = m;
}

__global__ void __launch_bounds__(224) kernel_j11_k(){   // j1 = 1 first order
    int i = blockIdx.x;            // bc*8 + l
    int bc = i >> 3, l = i & 7;
    chain112(g_xh + bc*IMG224, g_psi1 + l*IMG224, &g_feat[bc*81 + 9 + l]);
}
__global__ void __launch_bounds__(224) kernel_j2_k(){    // second order
    int i = blockIdx.x;            // bc*64 + l1*8 + l2
    int bc = i >> 6, l1 = (i >> 3) & 7, l2 = i & 7;
    chain112(g_u1h2 + (bc*8 + l1)*IMG224, g_psi1 + l2*IMG224,
             &g_feat[bc*81 + 17 + l1*8 + l2]);
}

// ---- s0 / s1(j1=0): fold4(src*phi0) -> ifft2@56 -> real -> max -------------
__global__ void __launch_bounds__(224) kernel_s56_k(){
    __shared__ float2 im[56*57];
    int i = blockIdx.x;            // [0,48): s0 ; [48,432): s1 j1=0
    const float2* src; int featIdx;
    if (i < 48){ src = g_xh + i*IMG224; featIdx = i*81; }
    else {
        int j = i - 48; int bc = j >> 3, l = j & 7;
        src = g_u1h2 + j*IMG224; featIdx = bc*81 + 1 + l;
    }
    int tid = threadIdx.x;
    for (int e = tid; e < 56*56; e += 224){
        int aa = e/56, bb = e - aa*56;
        float2 acc = make_float2(0.f, 0.f);
        #pragma unroll
        for (int p = 0; p < 4; p++)
            #pragma unroll
            for (int q = 0; q < 4; q++){
                int idx = (aa + 56*p)*224 + (bb + 56*q);
                float f = g_phi0[idx]; float2 uv = src[idx];
                acc.x = fmaf(uv.x, f, acc.x);
                acc.y = fmaf(uv.y, f, acc.y);
            }
        im[aa*57 + bb] = make_float2(acc.x*0.0625f, acc.y*0.0625f);
    }
    __syncthreads();
    fft2_56<true>(im);
    float mx = -FLT_MAX;
    for (int e = tid; e < 56*56; e += 224){
        int aa = e/56, bb = e - aa*56;
        mx = fmaxf(mx, im[aa*57 + bb].x);
    }
    float m = blockMax224(mx);
    if (tid == 0) g_feat[featIdx] = m;
}

// ---- final linear: out[b][o] = sum_k feat[b][k]*W[o][k] + bias[o] ----------
__global__ void linear_k(const float* __restrict__ W, const float* __restrict__ bias,
                         float* __restrict__ out){
    __shared__ float gs[243];
    int b = blockIdx.x;
    for (int k = threadIdx.x; k < 243; k += 256) gs[k] = g_feat[b*243 + k];
    __syncthreads();
    for (int o = threadIdx.x; o < 1000; o += 256){
        float acc = bias[o];
        const float* wr = W + o*243;
        #pragma unroll 3
        for (int k = 0; k < 243; k++) acc = fmaf(gs[k], wr[k], acc);
        out[b*1000 + o] = acc;
    }
}

// ---------------------------------------------------------------------------
extern "C" void kernel_launch(void* const* d_in, const int* in_sizes, int n_in,
                              void* d_out, int out_size){
    const float *x = nullptr, *W = nullptr, *bias = nullptr;
    for (int i = 0; i < n_in; i++){
        if      (in_sizes[i] == 16*3*224*224) x    = (const float*)d_in[i];
        else if (in_sizes[i] == 1000*243)     W    = (const float*)d_in[i];
        else if (in_sizes[i] == 1000)         bias = (const float*)d_in[i];
    }
    float* out = (float*)d_out;

    const int SM_CHAIN = (112*113 + 56*57) * (int)sizeof(float2); // 126784 B
    cudaFuncSetAttribute(kernel_j11_k, cudaFuncAttributeMaxDynamicSharedMemorySize, SM_CHAIN);
    cudaFuncSetAttribute(kernel_j2_k,  cudaFuncAttributeMaxDynamicSharedMemorySize, SM_CHAIN);

    int genTotal = 224 + 2*8*IMG224 + IMG224 + 112*112;
    gen_filters_k<<<(genTotal + 255)/256, 256>>>();

    pass224_k<0><<<dim3(32, 48),  224>>>(x);        // x -> scratch (rows fwd)
    pass224_k<1><<<dim3(32, 48),  224>>>(nullptr);  // scratch -> xh
    pass224_k<2><<<dim3(32, 384), 224>>>(nullptr);  // xh*psi0 -> scratch (inv)
    pass224_k<3><<<dim3(32, 384), 224>>>(nullptr);  // scratch -> u1 = |ifft2|
    pass224_k<4><<<dim3(32, 384), 224>>>(nullptr);  // u1 -> scratch (fwd)
    pass224_k<5><<<dim3(32, 384), 224>>>(nullptr);  // scratch -> u1h2

    kernel_s56_k<<<432, 224>>>();                   // s0 + s1(j1=0)
    kernel_j11_k<<<384, 224, SM_CHAIN>>>();         // s1(j1=1)
    kernel_j2_k<<<3072, 224, SM_CHAIN>>>();         // s2
    linear_k<<<16, 256>>>(W, bias, out);
    (void)out_size;
}

// round 3
// speedup vs baseline: 1.6192x; 1.6192x over previous
#include <cuda_runtime.h>
#include <math.h>
#include <float.h>

// ---------------------------------------------------------------------------
// Scattering2D (J=2, L=8, 224x224) B=16, C=3  + global max pool + linear.
// FFTs: 7-point DFT per lane x radix-2 shuffle FFT across G lanes.
// ---------------------------------------------------------------------------

#define IMG224 (224*224)

// ---- device global scratch -------------------------------------------------
__device__ float2 g_w224[224];
__device__ float  g_psi0[8*IMG224];      // j=0 Morlets @224
__device__ float  g_psi1[8*IMG224];      // j=1 Morlets @224
__device__ float  g_psi1T[8*IMG224];     // transposed j=1 Morlets (for transposed u1h2)
__device__ float  g_phi0[IMG224];        // phi @224 (transpose-symmetric)
__device__ float  g_phi1[112*112];       // phi folded to 112 (transpose-symmetric)
__device__ float2 g_xh[48*IMG224];       // fft2(x)
__device__ float2 g_s1buf[384*IMG224];   // scratch A
__device__ float2 g_s2buf[384*IMG224];   // scratch B
__device__ float2 g_u1h2[384*IMG224];    // fft2(|ifft2(xh*psi0)|)  [TRANSPOSED layout]
__device__ float  g_feat[48*81];         // scattering features

// ---- complex helpers -------------------------------------------------------
__device__ __forceinline__ float2 cmul(float2 a, float2 b){
    return make_float2(fmaf(a.x,b.x,-a.y*b.y), fmaf(a.x,b.y, a.y*b.x));
}
__device__ __forceinline__ float2 cfma(float2 a, float2 b, float2 c){
    float2 r;
    r.x = fmaf(a.x, b.x, fmaf(-a.y, b.y, c.x));
    r.y = fmaf(a.x, b.y, fmaf( a.y, b.x, c.y));
    return r;
}
template<bool INV>
__device__ __forceinline__ float2 twid(int t){
    float2 w = g_w224[t];
    if (INV) w.y = -w.y;
    return w;
}

// ---- core line FFT: 7 register values per lane, G = 1<<LOGG lanes ----------
// Input : a[n1] = x[G*n1 + gl].  Output: a[k1] = X[k1 + 7*bitrev(gl)].
template<int LOGG, bool INV>
__device__ __forceinline__ void fft_regs(float2 a[7], int gl){
    const int G  = 1 << LOGG;
    const int N  = 7 * G;
    const int ST = 224 / N;

    float2 w7[7];
    #pragma unroll
    for (int m = 0; m < 7; m++) w7[m] = twid<INV>(32*m);

    float2 A[7];
    #pragma unroll
    for (int k1 = 0; k1 < 7; k1++){
        float2 s = a[0];
        #pragma unroll
        for (int n1 = 1; n1 < 7; n1++) s = cfma(a[n1], w7[(n1*k1) % 7], s);
        A[k1] = s;
    }
    #pragma unroll
    for (int k1 = 1; k1 < 7; k1++)
        A[k1] = cmul(A[k1], twid<INV>(gl * k1 * ST));

    #pragma unroll
    for (int m = G/2; m >= 1; m >>= 1){
        const int tstep = 224 / (2*m);
        float2 w = twid<INV>((gl & (m-1)) * tstep);
        bool up = (gl & m) != 0;
        #pragma unroll
        for (int k1 = 0; k1 < 7; k1++){
            float2 mine = A[k1];
            float2 oth;
            oth.x = __shfl_xor_sync(0xffffffffu, mine.x, m, 32);
            oth.y = __shfl_xor_sync(0xffffffffu, mine.y, m, 32);
            if (up) A[k1] = cmul(make_float2(oth.x - mine.x, oth.y - mine.y), w);
            else    A[k1] = make_float2(mine.x + oth.x, mine.y + oth.y);
        }
    }
    if (INV){
        const float s = 1.0f / (float)N;
        #pragma unroll
        for (int k1 = 0; k1 < 7; k1++){ A[k1].x *= s; A[k1].y *= s; }
    }
    #pragma unroll
    for (int k1 = 0; k1 < 7; k1++) a[k1] = A[k1];
}

template<int LOGG, bool INV>
__device__ __forceinline__ void fft_line(float2* buf, int stride, int gl){
    const int G = 1 << LOGG;
    float2 a[7];
    #pragma unroll
    for (int n1 = 0; n1 < 7; n1++) a[n1] = buf[(n1*G + gl)*stride];
    fft_regs<LOGG, INV>(a, gl);
    int k2 = __brev((unsigned)gl) >> (32 - LOGG);
    #pragma unroll
    for (int k1 = 0; k1 < 7; k1++) buf[(k1 + 7*k2)*stride] = a[k1];
}

// ---- in-block 2D FFTs (448 threads) ----------------------------------------
template<bool INV>
__device__ __forceinline__ void fft2_112(float2* img){   // pitch 113
    int gl = threadIdx.x & 15, grp = threadIdx.x >> 4;   // 28 groups of 16
    for (int r = grp; r < 112; r += 28) fft_line<4, INV>(img + r*113, 1, gl);
    __syncthreads();
    for (int c = grp; c < 112; c += 28) fft_line<4, INV>(img + c, 113, gl);
    __syncthreads();
}
template<bool INV>
__device__ __forceinline__ void fft2_56(float2* img){    // pitch 57
    int gl = threadIdx.x & 7, grp = threadIdx.x >> 3;    // 56 groups of 8
    fft_line<3, INV>(img + grp*57, 1, gl);
    __syncthreads();
    fft_line<3, INV>(img + grp, 57, gl);
    __syncthreads();
}

__device__ __forceinline__ float blockMax448(float v){
    #pragma unroll
    for (int o = 16; o; o >>= 1) v = fmaxf(v, __shfl_xor_sync(0xffffffffu, v, o));
    __shared__ float red[14];
    int w = threadIdx.x >> 5;
    if ((threadIdx.x & 31) == 0) red[w] = v;
    __syncthreads();
    float m = -FLT_MAX;
    if (threadIdx.x == 0){
        #pragma unroll
        for (int i = 0; i < 14; i++) m = fmaxf(m, red[i]);
    }
    return m;
}

// ---- filter + twiddle generation (fp32 fast path, every call) --------------
__device__ __forceinline__ float ffreq(int a){
    const float PI = 3.14159265358979f;
    return 2.0f*PI*(float)((a < 112) ? a : a - 224) / 224.0f;
}
__global__ void gen_filters_k(){
    int t = blockIdx.x*256 + threadIdx.x;
    const float PI = 3.14159265358979f;
    if (t < 224){
        double ang = -2.0*3.14159265358979323846*(double)t/224.0;
        g_w224[t] = make_float2((float)cos(ang), (float)sin(ang));
        return;
    }
    int u = t - 224;
    if (u < 3*8*IMG224){
        int j = u / (8*IMG224); int r = u - j*(8*IMG224);
        int l = r / IMG224;     int e = r - l*IMG224;
        int aa = e / 224, bb = e - aa*224;
        float wx = ffreq(aa), wy = ffreq(bb);
        if (j == 2){ float tmp = wx; wx = wy; wy = tmp; }   // transposed psi1
        int sj = (j == 0) ? 0 : 1;
        float th = (float)l * (PI / 8.0f);
        float xi = (3.0f*PI/4.0f) / (float)(1 << sj);
        float sg = 0.8f * (float)(1 << sj);
        float ct = cosf(th), st = sinf(th);
        float uu =  ct*wx + st*wy;
        float vv = -st*wx + ct*wy;
        float vs = vv * 2.0f;                // / slant(=0.5)
        float s2 = 0.5f*sg*sg;
        float gab = expf(-s2*((uu-xi)*(uu-xi) + vs*vs));
        float gau = expf(-s2*(uu*uu + vs*vs));
        float kap = expf(-s2*xi*xi);
        float val = gab - kap*gau;
        if (j == 0)      g_psi0 [l*IMG224 + e] = val;
        else if (j == 1) g_psi1 [l*IMG224 + e] = val;
        else             g_psi1T[l*IMG224 + e] = val;
        return;
    }
    u -= 3*8*IMG224;
    if (u < IMG224){
        int aa = u/224, bb = u - aa*224;
        float wx = ffreq(aa), wy = ffreq(bb);
        float s2 = 0.5f*1.6f*1.6f;
        g_phi0[u] = expf(-s2*(wx*wx + wy*wy));
        return;
    }
    u -= IMG224;
    if (u < 112*112){
        int aa = u/112, bb = u - aa*112;
        float s2 = 0.5f*1.6f*1.6f, s = 0.0f;
        #pragma unroll
        for (int p = 0; p < 2; p++)
            #pragma unroll
            for (int q = 0; q < 2; q++){
                float wx = ffreq(aa + 112*p), wy = ffreq(bb + 112*q);
                s += expf(-s2*(wx*wx + wy*wy));
            }
        g_phi1[u] = s*0.25f;
    }
}

// ---- @224 pass: 16 rows/block (512 thr), row FFT + coalesced transposed write
// MODE 0: x(real)  fwd -> s1buf                 [48]
// MODE 1: s1buf    fwd -> xh                    [48]
// MODE 2: xh*psi0  inv -> s1buf                 [384]
// MODE 3: s1buf    inv -> |.| -> fwd -> s2buf   [384]  (fused modulus pass)
// MODE 4: s2buf    fwd -> u1h2                  [384]
template<int MODE>
__global__ void __launch_bounds__(512) pass224_k(const float* __restrict__ xin){
    constexpr bool IN_REAL  = (MODE == 0);
    constexpr bool MUL_FILT = (MODE == 2);
    constexpr bool INV      = (MODE == 2 || MODE == 3);

    __shared__ float2 sbuf[16][225];
    int i    = blockIdx.y;
    int w    = threadIdx.x >> 5, lane = threadIdx.x & 31;
    int row  = blockIdx.x*16 + w;

    const float* inR = nullptr; const float2* inC = nullptr; const float* filt = nullptr;
    float2* outp = nullptr;
    if constexpr (MODE == 0){ inR = xin + (size_t)i*IMG224;            outp = g_s1buf; }
    if constexpr (MODE == 1){ inC = g_s1buf + (size_t)i*IMG224;        outp = g_xh;    }
    if constexpr (MODE == 2){ inC = g_xh + (size_t)(i >> 3)*IMG224;
                              filt = g_psi0 + (size_t)(i & 7)*IMG224;  outp = g_s1buf; }
    if constexpr (MODE == 3){ inC = g_s1buf + (size_t)i*IMG224;        outp = g_s2buf; }
    if constexpr (MODE == 4){ inC = g_s2buf + (size_t)i*IMG224;        outp = g_u1h2;  }

    float2 a[7];
    #pragma unroll
    for (int n1 = 0; n1 < 7; n1++){
        int idx = row*224 + n1*32 + lane;
        float2 v;
        if constexpr (IN_REAL) v = make_float2(inR[idx], 0.f);
        else                   v = inC[idx];
        if constexpr (MUL_FILT){ float f = filt[idx]; v.x *= f; v.y *= f; }
        a[n1] = v;
    }
    fft_regs<5, INV>(a, lane);

    if constexpr (MODE == 3){
        // modulus (ifft2 now complete) + warp-local reorder + forward FFT
        float* rb = (float*)&sbuf[w][0];          // 450 floats per warp
        int k2m = __brev((unsigned)lane) >> 27;
        #pragma unroll
        for (int k1 = 0; k1 < 7; k1++)
            rb[k1 + 7*k2m] = sqrtf(a[k1].x*a[k1].x + a[k1].y*a[k1].y);
        __syncwarp();
        #pragma unroll
        for (int n1 = 0; n1 < 7; n1++) a[n1] = make_float2(rb[n1*32 + lane], 0.f);
        __syncwarp();
        fft_regs<5, false>(a, lane);
    }

    int k2 = __brev((unsigned)lane) >> 27;
    #pragma unroll
    for (int k1 = 0; k1 < 7; k1++) sbuf[w][k1 + 7*k2] = a[k1];
    __syncthreads();

    // coalesced transposed write: 16 consecutive float2 = one 128B line
    int rr   = threadIdx.x & 15;
    int kk   = threadIdx.x >> 4;
    int grow = blockIdx.x*16 + rr;
    float2* o = outp + (size_t)i*IMG224;
    #pragma unroll
    for (int it = 0; it < 7; it++){
        int k = kk + it*32;
        o[k*224 + grow] = sbuf[rr][k];
    }
}

// ---- fused @112 chain (448 thr, smem = 112x113 float2 only) ----------------
__device__ __forceinline__ void chain112(const float2* __restrict__ src,
                                         const float* __restrict__ psi,
                                         float* featOut){
    extern __shared__ float2 sm[];
    float2* img = sm;                   // 112 x 113
    int tid = threadIdx.x;

    for (int e = tid; e < 112*112; e += 448){
        int aa = e/112, bb = e - aa*112;
        float2 acc = make_float2(0.f, 0.f);
        #pragma unroll
        for (int p = 0; p < 2; p++)
            #pragma unroll
            for (int q = 0; q < 2; q++){
                int idx = (aa + 112*p)*224 + (bb + 112*q);
                float f = psi[idx]; float2 uv = src[idx];
                acc.x = fmaf(uv.x, f, acc.x);
                acc.y = fmaf(uv.y, f, acc.y);
            }
        img[aa*113 + bb] = make_float2(acc.x*0.25f, acc.y*0.25f);
    }
    __syncthreads();
    fft2_112<true>(img);
    for (int e = tid; e < 112*112; e += 448){
        int aa = e/112, bb = e - aa*112;
        float2 z = img[aa*113 + bb];
        img[aa*113 + bb] = make_float2(sqrtf(z.x*z.x + z.y*z.y), 0.f);
    }
    __syncthreads();
    fft2_112<false>(img);

    // phi fold to registers (7 outputs/thread), then overwrite img front as 56x57
    float2 r[7];
    #pragma unroll
    for (int it = 0; it < 7; it++){
        int e = tid + it*448;
        int aa = e/56, bb = e - aa*56;
        float2 acc = make_float2(0.f, 0.f);
        #pragma unroll
        for (int p = 0; p < 2; p++)
            #pragma unroll
            for (int q = 0; q < 2; q++){
                int ia = aa + 56*p, ib = bb + 56*q;
                float f = g_phi1[ia*112 + ib]; float2 uv = img[ia*113 + ib];
                acc.x = fmaf(uv.x, f, acc.x);
                acc.y = fmaf(uv.y, f, acc.y);
            }
        r[it] = make_float2(acc.x*0.25f, acc.y*0.25f);
    }
    __syncthreads();
    float2* im56 = sm;                  // 56 x 57 overlays img front
    #pragma unroll
    for (int it = 0; it < 7; it++){
        int e = tid + it*448;
        int aa = e/56, bb = e - aa*56;
        im56[aa*57 + bb] = r[it];
    }
    __syncthreads();
    fft2_56<true>(im56);
    float mx = -FLT_MAX;
    #pragma unroll
    for (int it = 0; it < 7; it++){
        int e = tid + it*448;
        int aa = e/56, bb = e - aa*56;
        mx = fmaxf(mx, im56[aa*57 + bb].x);
    }
    float m = blockMax448(mx);
    if (tid == 0) *featOut = m;
}

// merged j1=1 first order + second order (3456 blocks)
__global__ void __launch_bounds__(448, 2) scatter2_k(){
    int i = blockIdx.x;
    if (i < 384){
        int bc = i >> 3, l = i & 7;
        chain112(g_xh + (size_t)bc*IMG224, g_psi1 + (size_t)l*IMG224,
                 &g_feat[bc*81 + 9 + l]);
    } else {
        int v = i - 384;
        int bc = v >> 6, l1 = (v >> 3) & 7, l2 = v & 7;
        // u1h2 is stored transposed; psi1T compensates, phi1 symmetric, max invariant
        chain112(g_u1h2 + (size_t)(bc*8 + l1)*IMG224, g_psi1T + (size_t)l2*IMG224,
                 &g_feat[bc*81 + 17 + l1*8 + l2]);
    }
}

// ---- s0 / s1(j1=0): fold4(src*phi0) -> ifft2@56 -> real -> max -------------
__global__ void __launch_bounds__(448) kernel_s56_k(){
    __shared__ float2 im[56*57];
    int i = blockIdx.x;            // [0,48): s0 ; [48,432): s1 j1=0
    const float2* src; int featIdx;
    if (i < 48){ src = g_xh + (size_t)i*IMG224; featIdx = i*81; }
    else {
        int j = i - 48; int bc = j >> 3, l = j & 7;
        src = g_u1h2 + (size_t)j*IMG224; featIdx = bc*81 + 1 + l;
        // src transposed + phi0 symmetric -> transposed result, max invariant
    }
    int tid = threadIdx.x;
    #pragma unroll
    for (int it = 0; it < 7; it++){
        int e = tid + it*448;
        int aa = e/56, bb = e - aa*56;
        float2 acc = make_float2(0.f, 0.f);
        #pragma unroll
        for (int p = 0; p < 4; p++)
            #pragma unroll
            for (int q = 0; q < 4; q++){
                int idx = (aa + 56*p)*224 + (bb + 56*q);
                float f = g_phi0[idx]; float2 uv = src[idx];
                acc.x = fmaf(uv.x, f, acc.x);
                acc.y = fmaf(uv.y, f, acc.y);
            }
        im[aa*57 + bb] = make_float2(acc.x*0.0625f, acc.y*0.0625f);
    }
    __syncthreads();
    fft2_56<true>(im);
    float mx = -FLT_MAX;
    #pragma unroll
    for (int it = 0; it < 7; it++){
        int e = tid + it*448;
        int aa = e/56, bb = e - aa*56;
        mx = fmaxf(mx, im[aa*57 + bb].x);
    }
    float m = blockMax448(mx);
    if (tid == 0) g_feat[featIdx] = m;
}

// ---- final linear ----------------------------------------------------------
__global__ void linear_k(const float* __restrict__ W, const float* __restrict__ bias,
                         float* __restrict__ out){
    __shared__ float gs[243];
    int b = blockIdx.x;
    for (int k = threadIdx.x; k < 243; k += 256) gs[k] = g_feat[b*243 + k];
    __syncthreads();
    for (int o = threadIdx.x; o < 1000; o += 256){
        float acc = bias[o];
        const float* wr = W + o*243;
        #pragma unroll 3
        for (int k = 0; k < 243; k++) acc = fmaf(gs[k], wr[k], acc);
        out[b*1000 + o] = acc;
    }
}

// ---------------------------------------------------------------------------
extern "C" void kernel_launch(void* const* d_in, const int* in_sizes, int n_in,
                              void* d_out, int out_size){
    const float *x = nullptr, *W = nullptr, *bias = nullptr;
    for (int i = 0; i < n_in; i++){
        if      (in_sizes[i] == 16*3*224*224) x    = (const float*)d_in[i];
        else if (in_sizes[i] == 1000*243)     W    = (const float*)d_in[i];
        else if (in_sizes[i] == 1000)         bias = (const float*)d_in[i];
    }
    float* out = (float*)d_out;

    const int SM_CHAIN = 112*113*(int)sizeof(float2);  // 101,248 B
    cudaFuncSetAttribute(scatter2_k, cudaFuncAttributeMaxDynamicSharedMemorySize, SM_CHAIN);

    int genTotal = 224 + 3*8*IMG224 + IMG224 + 112*112;
    gen_filters_k<<<(genTotal + 255)/256, 256>>>();

    pass224_k<0><<<dim3(14, 48),  512>>>(x);        // x -> s1buf (rows fwd)
    pass224_k<1><<<dim3(14, 48),  512>>>(nullptr);  // s1buf -> xh
    pass224_k<2><<<dim3(14, 384), 512>>>(nullptr);  // xh*psi0 -> s1buf (inv)
    pass224_k<3><<<dim3(14, 384), 512>>>(nullptr);  // inv + |.| + fwd -> s2buf
    pass224_k<4><<<dim3(14, 384), 512>>>(nullptr);  // s2buf -> u1h2 (transposed)

    kernel_s56_k<<<432, 448>>>();                   // s0 + s1(j1=0)
    scatter2_k<<<3456, 448, SM_CHAIN>>>();          // s1(j1=1) + s2
    linear_k<<<16, 256>>>(W, bias, out);
    (void)out_size;
}

// round 4
// speedup vs baseline: 1.6470x; 1.0172x over previous
#include <cuda_runtime.h>
#include <math.h>
#include <float.h>

// ---------------------------------------------------------------------------
// Scattering2D (J=2, L=8, 224x224) B=16, C=3  + global max pool + linear.
// FFTs: 7-point DFT per lane x radix-2 shuffle FFT across G lanes.
// ---------------------------------------------------------------------------

#define IMG224 (224*224)
#define IMG112 (112*112)

// ---- device global scratch -------------------------------------------------
__device__ float2 g_w224[224];
__device__ float  g_psi0[8*IMG224];      // j=0 Morlets @224
__device__ float  g_psi1[8*IMG224];      // j=1 Morlets @224
__device__ float  g_psi1T[8*IMG224];     // transposed j=1 Morlets
__device__ float  g_phi0[IMG224];        // phi @224 (transpose-symmetric)
__device__ float  g_phi1[IMG112];        // phi folded to 112 (transpose-symmetric)
__device__ float2 g_xh[48*IMG224];       // fft2(x)
__device__ float2 g_s1buf[384*IMG224];   // scratch A
__device__ float2 g_s2buf[384*IMG224];   // scratch B
__device__ float2 g_u1h2[384*IMG224];    // fft2(|ifft2(xh*psi0)|)  [TRANSPOSED]
__device__ float2 g_fold[3456*IMG112];   // prefolded 112x112 inputs for chains
__device__ float  g_feat[48*81];         // scattering features

// ---- complex helpers -------------------------------------------------------
__device__ __forceinline__ float2 cmul(float2 a, float2 b){
    return make_float2(fmaf(a.x,b.x,-a.y*b.y), fmaf(a.x,b.y, a.y*b.x));
}
__device__ __forceinline__ float2 cfma(float2 a, float2 b, float2 c){
    float2 r;
    r.x = fmaf(a.x, b.x, fmaf(-a.y, b.y, c.x));
    r.y = fmaf(a.x, b.y, fmaf( a.y, b.x, c.y));
    return r;
}
template<bool INV>
__device__ __forceinline__ float2 twid(int t){
    float2 w = g_w224[t];
    if (INV) w.y = -w.y;
    return w;
}

// ---- core line FFT: 7 register values per lane, G = 1<<LOGG lanes ----------
// Input : a[n1] = x[G*n1 + gl].  Output: a[k1] = X[k1 + 7*bitrev(gl)].
template<int LOGG, bool INV>
__device__ __forceinline__ void fft_regs(float2 a[7], int gl){
    const int G  = 1 << LOGG;
    const int N  = 7 * G;
    const int ST = 224 / N;

    float2 w7[7];
    #pragma unroll
    for (int m = 0; m < 7; m++) w7[m] = twid<INV>(32*m);

    float2 A[7];
    #pragma unroll
    for (int k1 = 0; k1 < 7; k1++){
        float2 s = a[0];
        #pragma unroll
        for (int n1 = 1; n1 < 7; n1++) s = cfma(a[n1], w7[(n1*k1) % 7], s);
        A[k1] = s;
    }
    #pragma unroll
    for (int k1 = 1; k1 < 7; k1++)
        A[k1] = cmul(A[k1], twid<INV>(gl * k1 * ST));

    #pragma unroll
    for (int m = G/2; m >= 1; m >>= 1){
        const int tstep = 224 / (2*m);
        float2 w = twid<INV>((gl & (m-1)) * tstep);
        bool up = (gl & m) != 0;
        #pragma unroll
        for (int k1 = 0; k1 < 7; k1++){
            float2 mine = A[k1];
            float2 oth;
            oth.x = __shfl_xor_sync(0xffffffffu, mine.x, m, 32);
            oth.y = __shfl_xor_sync(0xffffffffu, mine.y, m, 32);
            if (up) A[k1] = cmul(make_float2(oth.x - mine.x, oth.y - mine.y), w);
            else    A[k1] = make_float2(mine.x + oth.x, mine.y + oth.y);
        }
    }
    if (INV){
        const float s = 1.0f / (float)N;
        #pragma unroll
        for (int k1 = 0; k1 < 7; k1++){ A[k1].x *= s; A[k1].y *= s; }
    }
    #pragma unroll
    for (int k1 = 0; k1 < 7; k1++) a[k1] = A[k1];
}

template<int LOGG, bool INV>
__device__ __forceinline__ void fft_line(float2* buf, int stride, int gl){
    const int G = 1 << LOGG;
    float2 a[7];
    #pragma unroll
    for (int n1 = 0; n1 < 7; n1++) a[n1] = buf[(n1*G + gl)*stride];
    fft_regs<LOGG, INV>(a, gl);
    int k2 = __brev((unsigned)gl) >> (32 - LOGG);
    #pragma unroll
    for (int k1 = 0; k1 < 7; k1++) buf[(k1 + 7*k2)*stride] = a[k1];
}

// ---- in-block 2D FFTs (448 threads) ----------------------------------------
template<bool INV>
__device__ __forceinline__ void fft2_112(float2* img){   // pitch 113
    int gl = threadIdx.x & 15, grp = threadIdx.x >> 4;   // 28 groups of 16
    for (int r = grp; r < 112; r += 28) fft_line<4, INV>(img + r*113, 1, gl);
    __syncthreads();
    for (int c = grp; c < 112; c += 28) fft_line<4, INV>(img + c, 113, gl);
    __syncthreads();
}
template<bool INV>
__device__ __forceinline__ void fft2_56(float2* img){    // pitch 57
    int gl = threadIdx.x & 7, grp = threadIdx.x >> 3;    // 56 groups of 8
    fft_line<3, INV>(img + grp*57, 1, gl);
    __syncthreads();
    fft_line<3, INV>(img + grp, 57, gl);
    __syncthreads();
}

__device__ __forceinline__ float blockMax448(float v){
    #pragma unroll
    for (int o = 16; o; o >>= 1) v = fmaxf(v, __shfl_xor_sync(0xffffffffu, v, o));
    __shared__ float red[14];
    int w = threadIdx.x >> 5;
    if ((threadIdx.x & 31) == 0) red[w] = v;
    __syncthreads();
    float m = -FLT_MAX;
    if (threadIdx.x == 0){
        #pragma unroll
        for (int i = 0; i < 14; i++) m = fmaxf(m, red[i]);
    }
    return m;
}

// ---- filter + twiddle generation (fp32 fast path, every call) --------------
__device__ __forceinline__ float ffreq(int a){
    const float PI = 3.14159265358979f;
    return 2.0f*PI*(float)((a < 112) ? a : a - 224) / 224.0f;
}
__global__ void gen_filters_k(){
    int t = blockIdx.x*256 + threadIdx.x;
    const float PI = 3.14159265358979f;
    if (t < 224){
        double ang = -2.0*3.14159265358979323846*(double)t/224.0;
        g_w224[t] = make_float2((float)cos(ang), (float)sin(ang));
        return;
    }
    int u = t - 224;
    if (u < 3*8*IMG224){
        int j = u / (8*IMG224); int r = u - j*(8*IMG224);
        int l = r / IMG224;     int e = r - l*IMG224;
        int aa = e / 224, bb = e - aa*224;
        float wx = ffreq(aa), wy = ffreq(bb);
        if (j == 2){ float tmp = wx; wx = wy; wy = tmp; }   // transposed psi1
        int sj = (j == 0) ? 0 : 1;
        float th = (float)l * (PI / 8.0f);
        float xi = (3.0f*PI/4.0f) / (float)(1 << sj);
        float sg = 0.8f * (float)(1 << sj);
        float ct = cosf(th), st = sinf(th);
        float uu =  ct*wx + st*wy;
        float vv = -st*wx + ct*wy;
        float vs = vv * 2.0f;                // / slant(=0.5)
        float s2 = 0.5f*sg*sg;
        float gab = expf(-s2*((uu-xi)*(uu-xi) + vs*vs));
        float gau = expf(-s2*(uu*uu + vs*vs));
        float kap = expf(-s2*xi*xi);
        float val = gab - kap*gau;
        if (j == 0)      g_psi0 [l*IMG224 + e] = val;
        else if (j == 1) g_psi1 [l*IMG224 + e] = val;
        else             g_psi1T[l*IMG224 + e] = val;
        return;
    }
    u -= 3*8*IMG224;
    if (u < IMG224){
        int aa = u/224, bb = u - aa*224;
        float wx = ffreq(aa), wy = ffreq(bb);
        float s2 = 0.5f*1.6f*1.6f;
        g_phi0[u] = expf(-s2*(wx*wx + wy*wy));
        return;
    }
    u -= IMG224;
    if (u < IMG112){
        int aa = u/112, bb = u - aa*112;
        float s2 = 0.5f*1.6f*1.6f, s = 0.0f;
        #pragma unroll
        for (int p = 0; p < 2; p++)
            #pragma unroll
            for (int q = 0; q < 2; q++){
                float wx = ffreq(aa + 112*p), wy = ffreq(bb + 112*q);
                s += expf(-s2*(wx*wx + wy*wy));
            }
        g_phi1[u] = s*0.25f;
    }
}

// ---- @224 pass: 16 rows/block (512 thr), row FFT + coalesced transposed write
template<int MODE>
__global__ void __launch_bounds__(512) pass224_k(const float* __restrict__ xin){
    constexpr bool IN_REAL  = (MODE == 0);
    constexpr bool MUL_FILT = (MODE == 2);
    constexpr bool INV      = (MODE == 2 || MODE == 3);

    __shared__ float2 sbuf[16][225];
    int i    = blockIdx.y;
    int w    = threadIdx.x >> 5, lane = threadIdx.x & 31;
    int row  = blockIdx.x*16 + w;

    const float* inR = nullptr; const float2* inC = nullptr; const float* filt = nullptr;
    float2* outp = nullptr;
    if constexpr (MODE == 0){ inR = xin + (size_t)i*IMG224;            outp = g_s1buf; }
    if constexpr (MODE == 1){ inC = g_s1buf + (size_t)i*IMG224;        outp = g_xh;    }
    if constexpr (MODE == 2){ inC = g_xh + (size_t)(i >> 3)*IMG224;
                              filt = g_psi0 + (size_t)(i & 7)*IMG224;  outp = g_s1buf; }
    if constexpr (MODE == 3){ inC = g_s1buf + (size_t)i*IMG224;        outp = g_s2buf; }
    if constexpr (MODE == 4){ inC = g_s2buf + (size_t)i*IMG224;        outp = g_u1h2;  }

    float2 a[7];
    #pragma unroll
    for (int n1 = 0; n1 < 7; n1++){
        int idx = row*224 + n1*32 + lane;
        float2 v;
        if constexpr (IN_REAL) v = make_float2(inR[idx], 0.f);
        else                   v = inC[idx];
        if constexpr (MUL_FILT){ float f = filt[idx]; v.x *= f; v.y *= f; }
        a[n1] = v;
    }
    fft_regs<5, INV>(a, lane);

    if constexpr (MODE == 3){
        // modulus (ifft2 complete) + warp-local reorder + forward FFT
        float* rb = (float*)&sbuf[w][0];
        int k2m = __brev((unsigned)lane) >> 27;
        #pragma unroll
        for (int k1 = 0; k1 < 7; k1++)
            rb[k1 + 7*k2m] = sqrtf(a[k1].x*a[k1].x + a[k1].y*a[k1].y);
        __syncwarp();
        #pragma unroll
        for (int n1 = 0; n1 < 7; n1++) a[n1] = make_float2(rb[n1*32 + lane], 0.f);
        __syncwarp();
        fft_regs<5, false>(a, lane);
    }

    int k2 = __brev((unsigned)lane) >> 27;
    #pragma unroll
    for (int k1 = 0; k1 < 7; k1++) sbuf[w][k1 + 7*k2] = a[k1];
    __syncthreads();

    int rr   = threadIdx.x & 15;
    int kk   = threadIdx.x >> 4;
    int grow = blockIdx.x*16 + rr;
    float2* o = outp + (size_t)i*IMG224;
    #pragma unroll
    for (int it = 0; it < 7; it++){
        int k = kk + it*32;
        o[k*224 + grow] = sbuf[rr][k];
    }
}

// ---- pre-fold kernel: reads each source ONCE, emits all 8 l2 folds ---------
// grid (7, 432): y<48 -> xh*psi1 (first order j1=1), y>=48 -> u1h2*psi1T (2nd).
__global__ void __launch_bounds__(512) fold2_k(){
    int s = blockIdx.y;
    const float2* src; const float* filt; int outBase;
    if (s < 48){ src = g_xh  + (size_t)s*IMG224;       filt = g_psi1;  outBase = s*8; }
    else       { src = g_u1h2 + (size_t)(s-48)*IMG224; filt = g_psi1T; outBase = 384 + (s-48)*8; }

    int base = blockIdx.x*1792;
    for (int e = base + threadIdx.x; e < base + 1792; e += 512){
        int aa = e/112, bb = e - aa*112;
        int i00 =  aa      *224 + bb, i01 =  aa      *224 + bb + 112;
        int i10 = (aa+112) *224 + bb, i11 = (aa+112) *224 + bb + 112;
        float2 s00 = src[i00], s01 = src[i01], s10 = src[i10], s11 = src[i11];
        #pragma unroll
        for (int l2 = 0; l2 < 8; l2++){
            const float* f = filt + (size_t)l2*IMG224;
            float f00 = f[i00], f01 = f[i01], f10 = f[i10], f11 = f[i11];
            float2 acc;
            acc.x = fmaf(s00.x,f00, fmaf(s01.x,f01, fmaf(s10.x,f10, s11.x*f11)));
            acc.y = fmaf(s00.y,f00, fmaf(s01.y,f01, fmaf(s10.y,f10, s11.y*f11)));
            g_fold[(size_t)(outBase + l2)*IMG112 + e] = make_float2(acc.x*0.25f, acc.y*0.25f);
        }
    }
}

// ---- fused @112 chain from prefolded input (448 thr, 101KB smem) -----------
__device__ __forceinline__ void chain112(const float2* __restrict__ fsrc,
                                         float* featOut){
    extern __shared__ float2 sm[];
    float2* img = sm;                   // 112 x 113
    int tid = threadIdx.x;
    int gl = tid & 15, grp = tid >> 4;  // 28 groups of 16

    // ifft2 row pass, loading straight from global (coalesced 128B per group)
    for (int r = grp; r < 112; r += 28){
        float2 a[7];
        #pragma unroll
        for (int n1 = 0; n1 < 7; n1++) a[n1] = fsrc[r*112 + n1*16 + gl];
        fft_regs<4, true>(a, gl);
        int k2 = __brev((unsigned)gl) >> 28;
        #pragma unroll
        for (int k1 = 0; k1 < 7; k1++) img[r*113 + k1 + 7*k2] = a[k1];
    }
    __syncthreads();
    // ifft2 col pass with fused modulus at write
    for (int c = grp; c < 112; c += 28){
        float2 a[7];
        #pragma unroll
        for (int n1 = 0; n1 < 7; n1++) a[n1] = img[(n1*16 + gl)*113 + c];
        fft_regs<4, true>(a, gl);
        int k2 = __brev((unsigned)gl) >> 28;
        #pragma unroll
        for (int k1 = 0; k1 < 7; k1++){
            float2 z = a[k1];
            img[(k1 + 7*k2)*113 + c] = make_float2(sqrtf(z.x*z.x + z.y*z.y), 0.f);
        }
    }
    __syncthreads();

    fft2_112<false>(img);               // forward fft2 of |u2|

    // phi fold to registers, then overwrite img front as 56x57
    float2 r[7];
    #pragma unroll
    for (int it = 0; it < 7; it++){
        int e = tid + it*448;
        int aa = e/56, bb = e - aa*56;
        float2 acc = make_float2(0.f, 0.f);
        #pragma unroll
        for (int p = 0; p < 2; p++)
            #pragma unroll
            for (int q = 0; q < 2; q++){
                int ia = aa + 56*p, ib = bb + 56*q;
                float f = g_phi1[ia*112 + ib]; float2 uv = img[ia*113 + ib];
                acc.x = fmaf(uv.x, f, acc.x);
                acc.y = fmaf(uv.y, f, acc.y);
            }
        r[it] = make_float2(acc.x*0.25f, acc.y*0.25f);
    }
    __syncthreads();
    float2* im56 = sm;                  // 56 x 57 overlays img front
    #pragma unroll
    for (int it = 0; it < 7; it++){
        int e = tid + it*448;
        int aa = e/56, bb = e - aa*56;
        im56[aa*57 + bb] = r[it];
    }
    __syncthreads();
    fft2_56<true>(im56);
    float mx = -FLT_MAX;
    #pragma unroll
    for (int it = 0; it < 7; it++){
        int e = tid + it*448;
        int aa = e/56, bb = e - aa*56;
        mx = fmaxf(mx, im56[aa*57 + bb].x);
    }
    float m = blockMax448(mx);
    if (tid == 0) *featOut = m;
}

// merged j1=1 first order + second order (3456 blocks)
__global__ void __launch_bounds__(448, 2) scatter2_k(){
    int i = blockIdx.x;
    int featIdx;
    if (i < 384){
        int bc = i >> 3, l = i & 7;
        featIdx = bc*81 + 9 + l;
    } else {
        int v = i - 384;
        int bc = v >> 6, l1 = (v >> 3) & 7, l2 = v & 7;
        featIdx = bc*81 + 17 + l1*8 + l2;
    }
    chain112(g_fold + (size_t)i*IMG112, &g_feat[featIdx]);
}

// ---- s0 / s1(j1=0): fold4(src*phi0) -> ifft2@56 -> real -> max -------------
__global__ void __launch_bounds__(448) kernel_s56_k(){
    __shared__ float2 im[56*57];
    int i = blockIdx.x;            // [0,48): s0 ; [48,432): s1 j1=0
    const float2* src; int featIdx;
    if (i < 48){ src = g_xh + (size_t)i*IMG224; featIdx = i*81; }
    else {
        int j = i - 48; int bc = j >> 3, l = j & 7;
        src = g_u1h2 + (size_t)j*IMG224; featIdx = bc*81 + 1 + l;
        // src transposed + phi0 symmetric -> transposed result, max invariant
    }
    int tid = threadIdx.x;
    #pragma unroll
    for (int it = 0; it < 7; it++){
        int e = tid + it*448;
        int aa = e/56, bb = e - aa*56;
        float2 acc = make_float2(0.f, 0.f);
        #pragma unroll
        for (int p = 0; p < 4; p++)
            #pragma unroll
            for (int q = 0; q < 4; q++){
                int idx = (aa + 56*p)*224 + (bb + 56*q);
                float f = g_phi0[idx]; float2 uv = src[idx];
                acc.x = fmaf(uv.x, f, acc.x);
                acc.y = fmaf(uv.y, f, acc.y);
            }
        im[aa*57 + bb] = make_float2(acc.x*0.0625f, acc.y*0.0625f);
    }
    __syncthreads();
    fft2_56<true>(im);
    float mx = -FLT_MAX;
    #pragma unroll
    for (int it = 0; it < 7; it++){
        int e = tid + it*448;
        int aa = e/56, bb = e - aa*56;
        mx = fmaxf(mx, im[aa*57 + bb].x);
    }
    float m = blockMax448(mx);
    if (tid == 0) g_feat[featIdx] = m;
}

// ---- final linear ----------------------------------------------------------
__global__ void linear_k(const float* __restrict__ W, const float* __restrict__ bias,
                         float* __restrict__ out){
    __shared__ float gs[243];
    int b = blockIdx.x;
    for (int k = threadIdx.x; k < 243; k += 256) gs[k] = g_feat[b*243 + k];
    __syncthreads();
    for (int o = threadIdx.x; o < 1000; o += 256){
        float acc = bias[o];
        const float* wr = W + o*243;
        #pragma unroll 3
        for (int k = 0; k < 243; k++) acc = fmaf(gs[k], wr[k], acc);
        out[b*1000 + o] = acc;
    }
}

// ---------------------------------------------------------------------------
extern "C" void kernel_launch(void* const* d_in, const int* in_sizes, int n_in,
                              void* d_out, int out_size){
    const float *x = nullptr, *W = nullptr, *bias = nullptr;
    for (int i = 0; i < n_in; i++){
        if      (in_sizes[i] == 16*3*224*224) x    = (const float*)d_in[i];
        else if (in_sizes[i] == 1000*243)     W    = (const float*)d_in[i];
        else if (in_sizes[i] == 1000)         bias = (const float*)d_in[i];
    }
    float* out = (float*)d_out;

    const int SM_CHAIN = 112*113*(int)sizeof(float2);  // 101,248 B
    cudaFuncSetAttribute(scatter2_k, cudaFuncAttributeMaxDynamicSharedMemorySize, SM_CHAIN);

    int genTotal = 224 + 3*8*IMG224 + IMG224 + IMG112;
    gen_filters_k<<<(genTotal + 255)/256, 256>>>();

    pass224_k<0><<<dim3(14, 48),  512>>>(x);        // x -> s1buf (rows fwd)
    pass224_k<1><<<dim3(14, 48),  512>>>(nullptr);  // s1buf -> xh
    pass224_k<2><<<dim3(14, 384), 512>>>(nullptr);  // xh*psi0 -> s1buf (inv)
    pass224_k<3><<<dim3(14, 384), 512>>>(nullptr);  // inv + |.| + fwd -> s2buf
    pass224_k<4><<<dim3(14, 384), 512>>>(nullptr);  // s2buf -> u1h2 (transposed)

    fold2_k<<<dim3(7, 432), 512>>>();               // prefold all 3456 chain inputs
    kernel_s56_k<<<432, 448>>>();                   // s0 + s1(j1=0)
    scatter2_k<<<3456, 448, SM_CHAIN>>>();          // s1(j1=1) + s2
    linear_k<<<16, 256>>>(W, bias, out);
    (void)out_size;
}

// round 5
// speedup vs baseline: 1.9435x; 1.1800x over previous
#include <cuda_runtime.h>
#include <math.h>
#include <float.h>

// ---------------------------------------------------------------------------
// Scattering2D (J=2, L=8, 224x224) B=16, C=3  + global max pool + linear.
// FFTs: 7-point DFT per lane x radix-2 shuffle FFT across G lanes.
// Low-pass (phi) stages implemented as EXACT spatial separable Gaussian blurs
// (IDFT of the sampled spectrum; tails < 4e-6) + stride subsampling.
// ---------------------------------------------------------------------------

#define IMG224 (224*224)
#define IMG112 (112*112)

// ---- device global scratch -------------------------------------------------
__device__ float2 g_w224[224];
__device__ float  g_psi0[8*IMG224];      // j=0 Morlets @224
__device__ float  g_psi1[8*IMG224];      // j=1 Morlets @224
__device__ float  g_psi1T[8*IMG224];     // transposed j=1 Morlets
__device__ float  g_h0[21];              // spatial phi taps @224 (stride-4 path)
__device__ float  g_h1[11];              // spatial phi taps @112 (stride-2 path)
__device__ float2 g_xh[48*IMG224];       // fft2(x)
__device__ float2 g_s1buf[384*IMG224];   // scratch A
__device__ float2 g_s2buf[384*IMG224];   // scratch B
__device__ float2 g_u1h2[384*IMG224];    // fft2(u1)  [TRANSPOSED layout]
__device__ float  g_u1[384*IMG224];      // spatial u1 [TRANSPOSED layout]
__device__ float2 g_fold[3456*IMG112];   // prefolded 112x112 chain inputs
__device__ float  g_feat[48*81];         // scattering features

// ---- complex helpers -------------------------------------------------------
__device__ __forceinline__ float2 cmul(float2 a, float2 b){
    return make_float2(fmaf(a.x,b.x,-a.y*b.y), fmaf(a.x,b.y, a.y*b.x));
}
__device__ __forceinline__ float2 cfma(float2 a, float2 b, float2 c){
    float2 r;
    r.x = fmaf(a.x, b.x, fmaf(-a.y, b.y, c.x));
    r.y = fmaf(a.x, b.y, fmaf( a.y, b.x, c.y));
    return r;
}
template<bool INV>
__device__ __forceinline__ float2 twid(int t){
    float2 w = g_w224[t];
    if (INV) w.y = -w.y;
    return w;
}

// ---- core line FFT: 7 register values per lane, G = 1<<LOGG lanes ----------
template<int LOGG, bool INV>
__device__ __forceinline__ void fft_regs(float2 a[7], int gl){
    const int G  = 1 << LOGG;
    const int N  = 7 * G;
    const int ST = 224 / N;

    float2 w7[7];
    #pragma unroll
    for (int m = 0; m < 7; m++) w7[m] = twid<INV>(32*m);

    float2 A[7];
    #pragma unroll
    for (int k1 = 0; k1 < 7; k1++){
        float2 s = a[0];
        #pragma unroll
        for (int n1 = 1; n1 < 7; n1++) s = cfma(a[n1], w7[(n1*k1) % 7], s);
        A[k1] = s;
    }
    #pragma unroll
    for (int k1 = 1; k1 < 7; k1++)
        A[k1] = cmul(A[k1], twid<INV>(gl * k1 * ST));

    #pragma unroll
    for (int m = G/2; m >= 1; m >>= 1){
        const int tstep = 224 / (2*m);
        float2 w = twid<INV>((gl & (m-1)) * tstep);
        bool up = (gl & m) != 0;
        #pragma unroll
        for (int k1 = 0; k1 < 7; k1++){
            float2 mine = A[k1];
            float2 oth;
            oth.x = __shfl_xor_sync(0xffffffffu, mine.x, m, 32);
            oth.y = __shfl_xor_sync(0xffffffffu, mine.y, m, 32);
            if (up) A[k1] = cmul(make_float2(oth.x - mine.x, oth.y - mine.y), w);
            else    A[k1] = make_float2(mine.x + oth.x, mine.y + oth.y);
        }
    }
    if (INV){
        const float s = 1.0f / (float)N;
        #pragma unroll
        for (int k1 = 0; k1 < 7; k1++){ A[k1].x *= s; A[k1].y *= s; }
    }
    #pragma unroll
    for (int k1 = 0; k1 < 7; k1++) a[k1] = A[k1];
}

__device__ __forceinline__ float blockMax448(float v){
    #pragma unroll
    for (int o = 16; o; o >>= 1) v = fmaxf(v, __shfl_xor_sync(0xffffffffu, v, o));
    __shared__ float red[14];
    int w = threadIdx.x >> 5;
    if ((threadIdx.x & 31) == 0) red[w] = v;
    __syncthreads();
    float m = -FLT_MAX;
    if (threadIdx.x == 0){
        #pragma unroll
        for (int i = 0; i < 14; i++) m = fmaxf(m, red[i]);
    }
    return m;
}

// ---- filter + twiddle + tap generation (every call) ------------------------
__device__ __forceinline__ float ffreq(int a){
    const float PI = 3.14159265358979f;
    return 2.0f*PI*(float)((a < 112) ? a : a - 224) / 224.0f;
}
__global__ void gen_filters_k(){
    int t = blockIdx.x*256 + threadIdx.x;
    const float PI = 3.14159265358979f;
    if (t < 224){
        double ang = -2.0*3.14159265358979323846*(double)t/224.0;
        g_w224[t] = make_float2((float)cos(ang), (float)sin(ang));
        return;
    }
    int u = t - 224;
    if (u < 3*8*IMG224){
        int j = u / (8*IMG224); int r = u - j*(8*IMG224);
        int l = r / IMG224;     int e = r - l*IMG224;
        int aa = e / 224, bb = e - aa*224;
        float wx = ffreq(aa), wy = ffreq(bb);
        if (j == 2){ float tmp = wx; wx = wy; wy = tmp; }   // transposed psi1
        int sj = (j == 0) ? 0 : 1;
        float th = (float)l * (PI / 8.0f);
        float xi = (3.0f*PI/4.0f) / (float)(1 << sj);
        float sg = 0.8f * (float)(1 << sj);
        float ct = cosf(th), st = sinf(th);
        float uu =  ct*wx + st*wy;
        float vv = -st*wx + ct*wy;
        float vs = vv * 2.0f;                // / slant(=0.5)
        float s2 = 0.5f*sg*sg;
        float gab = expf(-s2*((uu-xi)*(uu-xi) + vs*vs));
        float gau = expf(-s2*(uu*uu + vs*vs));
        float kap = expf(-s2*xi*xi);
        float val = gab - kap*gau;
        if (j == 0)      g_psi0 [l*IMG224 + e] = val;
        else if (j == 1) g_psi1 [l*IMG224 + e] = val;
        else             g_psi1T[l*IMG224 + e] = val;
        return;
    }
    u -= 3*8*IMG224;
    if (u < 32){
        // exact spatial taps: h[n] = (1/224) sum_k exp(-1.28 w_k^2) cos(2 pi k n / 224)
        int n, stride;
        if (u < 21){ n = u - 10; stride = 1; }              // g_h0 (224 grid)
        else       { n = u - 21 - 5; stride = 2; }          // g_h1 = h0 at even offsets
        float s = 0.f;
        for (int k = 0; k < 224; k++){
            float w = ffreq(k);
            float ang = 2.0f*PI*(float)(k*n*stride)/224.0f;
            s += expf(-1.28f*w*w) * cosf(ang);
        }
        s /= 224.0f;
        if (u < 21) g_h0[u] = s;
        else        g_h1[u-21] = s;
    }
}

// ---- @224 pass: 16 rows/block (512 thr), row FFT + coalesced transposed write
template<int MODE>
__global__ void __launch_bounds__(512) pass224_k(const float* __restrict__ xin){
    constexpr bool IN_REAL  = (MODE == 0);
    constexpr bool MUL_FILT = (MODE == 2);
    constexpr bool INV      = (MODE == 2 || MODE == 3);

    __shared__ float2 sbuf[16][225];
    int i    = blockIdx.y;
    int w    = threadIdx.x >> 5, lane = threadIdx.x & 31;
    int row  = blockIdx.x*16 + w;

    const float* inR = nullptr; const float2* inC = nullptr; const float* filt = nullptr;
    float2* outp = nullptr;
    if constexpr (MODE == 0){ inR = xin + (size_t)i*IMG224;            outp = g_s1buf; }
    if constexpr (MODE == 1){ inC = g_s1buf + (size_t)i*IMG224;        outp = g_xh;    }
    if constexpr (MODE == 2){ inC = g_xh + (size_t)(i >> 3)*IMG224;
                              filt = g_psi0 + (size_t)(i & 7)*IMG224;  outp = g_s1buf; }
    if constexpr (MODE == 3){ inC = g_s1buf + (size_t)i*IMG224;        outp = g_s2buf; }
    if constexpr (MODE == 4){ inC = g_s2buf + (size_t)i*IMG224;        outp = g_u1h2;  }

    float2 a[7];
    #pragma unroll
    for (int n1 = 0; n1 < 7; n1++){
        int idx = row*224 + n1*32 + lane;
        float2 v;
        if constexpr (IN_REAL) v = make_float2(inR[idx], 0.f);
        else                   v = inC[idx];
        if constexpr (MUL_FILT){ float f = filt[idx]; v.x *= f; v.y *= f; }
        a[n1] = v;
    }
    fft_regs<5, INV>(a, lane);

    if constexpr (MODE == 3){
        // modulus (ifft2 complete) -> save spatial u1 -> forward FFT
        float* rb = (float*)&sbuf[w][0];
        int k2m = __brev((unsigned)lane) >> 27;
        #pragma unroll
        for (int k1 = 0; k1 < 7; k1++)
            rb[k1 + 7*k2m] = sqrtf(a[k1].x*a[k1].x + a[k1].y*a[k1].y);
        __syncwarp();
        float* u1o = g_u1 + (size_t)i*IMG224 + row*224;
        #pragma unroll
        for (int n1 = 0; n1 < 7; n1++){
            float v = rb[n1*32 + lane];
            u1o[n1*32 + lane] = v;
            a[n1] = make_float2(v, 0.f);
        }
        __syncwarp();
        fft_regs<5, false>(a, lane);
    }

    int k2 = __brev((unsigned)lane) >> 27;
    #pragma unroll
    for (int k1 = 0; k1 < 7; k1++) sbuf[w][k1 + 7*k2] = a[k1];
    __syncthreads();

    int rr   = threadIdx.x & 15;
    int kk   = threadIdx.x >> 4;
    int grow = blockIdx.x*16 + rr;
    float2* o = outp + (size_t)i*IMG224;
    #pragma unroll
    for (int it = 0; it < 7; it++){
        int k = kk + it*32;
        o[k*224 + grow] = sbuf[rr][k];
    }
}

// ---- pre-fold kernel: reads each source ONCE, emits all 8 l2 folds ---------
__global__ void __launch_bounds__(512) fold2_k(){
    int s = blockIdx.y;
    const float2* src; const float* filt; int outBase;
    if (s < 48){ src = g_xh  + (size_t)s*IMG224;       filt = g_psi1;  outBase = s*8; }
    else       { src = g_u1h2 + (size_t)(s-48)*IMG224; filt = g_psi1T; outBase = 384 + (s-48)*8; }

    int base = blockIdx.x*1792;
    for (int e = base + threadIdx.x; e < base + 1792; e += 512){
        int aa = e/112, bb = e - aa*112;
        int i00 =  aa      *224 + bb, i01 =  aa      *224 + bb + 112;
        int i10 = (aa+112) *224 + bb, i11 = (aa+112) *224 + bb + 112;
        float2 s00 = src[i00], s01 = src[i01], s10 = src[i10], s11 = src[i11];
        #pragma unroll
        for (int l2 = 0; l2 < 8; l2++){
            const float* f = filt + (size_t)l2*IMG224;
            float f00 = f[i00], f01 = f[i01], f10 = f[i10], f11 = f[i11];
            float2 acc;
            acc.x = fmaf(s00.x,f00, fmaf(s01.x,f01, fmaf(s10.x,f10, s11.x*f11)));
            acc.y = fmaf(s00.y,f00, fmaf(s01.y,f01, fmaf(s10.y,f10, s11.y*f11)));
            g_fold[(size_t)(outBase + l2)*IMG112 + e] = make_float2(acc.x*0.25f, acc.y*0.25f);
        }
    }
}

// ---- fused @112 chain: ifft2 -> |.| -> separable blur (stride 2) -> max ----
__device__ __forceinline__ void chain112(const float2* __restrict__ fsrc,
                                         float* featOut){
    extern __shared__ float2 sm[];
    float2* img = sm;                   // 112 x 113 complex
    float*  smf = (float*)sm;           // float view
    __shared__ float sh_h[11];
    int tid = threadIdx.x;
    if (tid < 11) sh_h[tid] = g_h1[tid];
    int gl = tid & 15, grp = tid >> 4;  // 28 groups of 16

    // ifft2 row pass, loading straight from global
    for (int r = grp; r < 112; r += 28){
        float2 a[7];
        #pragma unroll
        for (int n1 = 0; n1 < 7; n1++) a[n1] = fsrc[r*112 + n1*16 + gl];
        fft_regs<4, true>(a, gl);
        int k2 = __brev((unsigned)gl) >> 28;
        #pragma unroll
        for (int k1 = 0; k1 < 7; k1++) img[r*113 + k1 + 7*k2] = a[k1];
    }
    __syncthreads();
    // ifft2 col pass, modulus stored into .x slots
    for (int c = grp; c < 112; c += 28){
        float2 a[7];
        #pragma unroll
        for (int n1 = 0; n1 < 7; n1++) a[n1] = img[(n1*16 + gl)*113 + c];
        fft_regs<4, true>(a, gl);
        int k2 = __brev((unsigned)gl) >> 28;
        #pragma unroll
        for (int k1 = 0; k1 < 7; k1++){
            float2 z = a[k1];
            smf[((k1 + 7*k2)*113 + c)*2] = sqrtf(z.x*z.x + z.y*z.y);
        }
    }
    __syncthreads();

    // horizontal blur at stride-2 output columns: hb[r][c] (112 x 56)
    float rh[14];
    #pragma unroll
    for (int it = 0; it < 14; it++){
        int e = tid + it*448;
        int r = e % 112, c = e / 112;
        float acc = 0.f;
        #pragma unroll
        for (int d = 0; d < 11; d++){
            int cc = 2*c + d - 5;
            if (cc < 0) cc += 112; else if (cc >= 112) cc -= 112;
            acc = fmaf(sh_h[d], smf[(r*113 + cc)*2], acc);
        }
        rh[it] = acc;
    }
    __syncthreads();
    #pragma unroll
    for (int it = 0; it < 14; it++){
        int e = tid + it*448;
        int r = e % 112, c = e / 112;
        smf[r*57 + c] = rh[it];          // hb overlay, pitch 57 (conflict-free)
    }
    __syncthreads();

    // vertical blur at stride-2 output rows + max
    float mx = -FLT_MAX;
    #pragma unroll
    for (int it = 0; it < 7; it++){
        int e = tid + it*448;
        int a = e / 56, b = e % 56;
        float acc = 0.f;
        #pragma unroll
        for (int d = 0; d < 11; d++){
            int rr = 2*a + d - 5;
            if (rr < 0) rr += 112; else if (rr >= 112) rr -= 112;
            acc = fmaf(sh_h[d], smf[rr*57 + b], acc);
        }
        mx = fmaxf(mx, acc);
    }
    float m = blockMax448(mx);
    if (tid == 0) *featOut = m;
}

// merged j1=1 first order + second order (3456 blocks)
__global__ void __launch_bounds__(448, 2) scatter2_k(){
    int i = blockIdx.x;
    int featIdx;
    if (i < 384){
        int bc = i >> 3, l = i & 7;
        featIdx = bc*81 + 9 + l;
    } else {
        int v = i - 384;
        int bc = v >> 6, l1 = (v >> 3) & 7, l2 = v & 7;
        featIdx = bc*81 + 17 + l1*8 + l2;
    }
    chain112(g_fold + (size_t)i*IMG112, &g_feat[featIdx]);
}

// ---- s0 / s1(j1=0): spatial blur @224, stride 4, circular, + max -----------
__global__ void __launch_bounds__(448) blur224_k(const float* __restrict__ x){
    __shared__ float hb[224*57];        // 51KB
    __shared__ float sh_h[21];
    int i = blockIdx.x;                 // [0,48): s0 from x ; [48,432): s1 j1=0 from u1
    const float* src; int featIdx;
    if (i < 48){ src = x + (size_t)i*IMG224; featIdx = i*81; }
    else {
        int j = i - 48;
        src = g_u1 + (size_t)j*IMG224;
        featIdx = (j >> 3)*81 + 1 + (j & 7);
    }
    int tid = threadIdx.x;
    if (tid < 21) sh_h[tid] = g_h0[tid];
    __syncthreads();

    int rr = tid / 56, c = tid % 56;    // 8 rows x 56 cols per sweep
    for (int r0 = 0; r0 < 224; r0 += 8){
        int r = r0 + rr;
        float acc = 0.f;
        #pragma unroll
        for (int d = 0; d < 21; d++){
            int cc = 4*c + d - 10;
            if (cc < 0) cc += 224; else if (cc >= 224) cc -= 224;
            acc = fmaf(sh_h[d], __ldg(src + r*224 + cc), acc);
        }
        hb[r*57 + c] = acc;
    }
    __syncthreads();

    float mx = -FLT_MAX;
    #pragma unroll
    for (int it = 0; it < 7; it++){
        int e = tid + it*448;
        int a = e / 56, b = e % 56;
        float acc = 0.f;
        #pragma unroll
        for (int d = 0; d < 21; d++){
            int r2 = 4*a + d - 10;
            if (r2 < 0) r2 += 224; else if (r2 >= 224) r2 -= 224;
            acc = fmaf(sh_h[d], hb[r2*57 + b], acc);
        }
        mx = fmaxf(mx, acc);
    }
    float m = blockMax448(mx);
    if (tid == 0) g_feat[featIdx] = m;
}

// ---- final linear ----------------------------------------------------------
__global__ void linear_k(const float* __restrict__ W, const float* __restrict__ bias,
                         float* __restrict__ out){
    __shared__ float gs[243];
    int b = blockIdx.x;
    for (int k = threadIdx.x; k < 243; k += 256) gs[k] = g_feat[b*243 + k];
    __syncthreads();
    for (int o = threadIdx.x; o < 1000; o += 256){
        float acc = bias[o];
        const float* wr = W + o*243;
        #pragma unroll 3
        for (int k = 0; k < 243; k++) acc = fmaf(gs[k], wr[k], acc);
        out[b*1000 + o] = acc;
    }
}

// ---------------------------------------------------------------------------
extern "C" void kernel_launch(void* const* d_in, const int* in_sizes, int n_in,
                              void* d_out, int out_size){
    const float *x = nullptr, *W = nullptr, *bias = nullptr;
    for (int i = 0; i < n_in; i++){
        if      (in_sizes[i] == 16*3*224*224) x    = (const float*)d_in[i];
        else if (in_sizes[i] == 1000*243)     W    = (const float*)d_in[i];
        else if (in_sizes[i] == 1000)         bias = (const float*)d_in[i];
    }
    float* out = (float*)d_out;

    const int SM_CHAIN = 112*113*(int)sizeof(float2);  // 101,248 B
    cudaFuncSetAttribute(scatter2_k, cudaFuncAttributeMaxDynamicSharedMemorySize, SM_CHAIN);

    int genTotal = 224 + 3*8*IMG224 + 32;
    gen_filters_k<<<(genTotal + 255)/256, 256>>>();

    pass224_k<0><<<dim3(14, 48),  512>>>(x);        // x -> s1buf (rows fwd)
    pass224_k<1><<<dim3(14, 48),  512>>>(nullptr);  // s1buf -> xh
    pass224_k<2><<<dim3(14, 384), 512>>>(nullptr);  // xh*psi0 -> s1buf (inv)
    pass224_k<3><<<dim3(14, 384), 512>>>(nullptr);  // inv + |.| -> u1, fwd -> s2buf
    pass224_k<4><<<dim3(14, 384), 512>>>(nullptr);  // s2buf -> u1h2 (transposed)

    fold2_k<<<dim3(7, 432), 512>>>();               // prefold all 3456 chain inputs
    blur224_k<<<432, 448>>>(x);                     // s0 + s1(j1=0) via spatial blur
    scatter2_k<<<3456, 448, SM_CHAIN>>>();          // s1(j1=1) + s2
    linear_k<<<16, 256>>>(W, bias, out);
    (void)out_size;
}

// round 6
// speedup vs baseline: 2.0850x; 1.0728x over previous
#include <cuda_runtime.h>
#include <math.h>
#include <float.h>

// ---------------------------------------------------------------------------
// Scattering2D (J=2, L=8, 224x224) B=16, C=3  + global max pool + linear.
// FFTs: symmetric-pair 7-point DFT per lane x radix-2 shuffle FFT across lanes.
// Low-pass (phi) stages are exact spatial separable Gaussian blurs.
// ---------------------------------------------------------------------------

#define IMG224 (224*224)
#define IMG112 (112*112)

// ---- device global scratch -------------------------------------------------
__device__ float2 g_w224[224];
__device__ float  g_psi0[8*IMG224];      // j=0 Morlets @224
__device__ float  g_psi1[8*IMG224];      // j=1 Morlets @224
__device__ float  g_psi1T[8*IMG224];     // transposed j=1 Morlets
__device__ float  g_h0[21];              // spatial phi taps @224 (stride-4 path)
__device__ float  g_h1[11];              // spatial phi taps @112 (stride-2 path)
__device__ float2 g_xh[48*IMG224];       // fft2(x)
__device__ float2 g_s1buf[384*IMG224];   // scratch A
__device__ float2 g_s2buf[384*IMG224];   // scratch B
__device__ float2 g_u1h2[384*IMG224];    // fft2(u1)  [TRANSPOSED layout]
__device__ float  g_u1[384*IMG224];      // spatial u1 [TRANSPOSED layout]
__device__ float2 g_fold[3456*IMG112];   // prefolded 112x112 chain inputs
__device__ float  g_feat[48*81];         // scattering features

// ---- complex helpers -------------------------------------------------------
__device__ __forceinline__ float2 cmul(float2 a, float2 b){
    return make_float2(fmaf(a.x,b.x,-a.y*b.y), fmaf(a.x,b.y, a.y*b.x));
}
template<bool INV>
__device__ __forceinline__ float2 twid(int t){
    float2 w = g_w224[t];
    if (INV) w.y = -w.y;
    return w;
}

// ---- core line FFT: symmetric-pair 7-pt DFT + radix-2 shuffle stages -------
// Input : a[n1] = x[G*n1 + gl].  Output: a[k1] = X[k1 + 7*bitrev(gl)].
template<int LOGG, bool INV>
__device__ __forceinline__ void fft_regs(float2 a[7], int gl){
    const int G  = 1 << LOGG;
    const int N  = 7 * G;
    const int ST = 224 / N;

    // 7-point DFT via conjugate-pair symmetry (~66 flops vs 144 naive)
    float2 w1 = twid<INV>(32), w2 = twid<INV>(64), w3 = twid<INV>(96);
    float2 a0 = a[0];
    float2 s1 = make_float2(a[1].x+a[6].x, a[1].y+a[6].y);
    float2 s2 = make_float2(a[2].x+a[5].x, a[2].y+a[5].y);
    float2 s3 = make_float2(a[3].x+a[4].x, a[3].y+a[4].y);
    float2 d1 = make_float2(a[1].x-a[6].x, a[1].y-a[6].y);
    float2 d2 = make_float2(a[2].x-a[5].x, a[2].y-a[5].y);
    float2 d3 = make_float2(a[3].x-a[4].x, a[3].y-a[4].y);

    float2 A[7];
    A[0] = make_float2(a0.x + s1.x + s2.x + s3.x,
                       a0.y + s1.y + s2.y + s3.y);
    {   // k=1: (c1,i1)(c2,i2)(c3,i3)
        float px = fmaf(w1.x,s1.x, fmaf(w2.x,s2.x, fmaf(w3.x,s3.x, a0.x)));
        float py = fmaf(w1.x,s1.y, fmaf(w2.x,s2.y, fmaf(w3.x,s3.y, a0.y)));
        float qx = fmaf(w1.y,d1.x, fmaf(w2.y,d2.x, w3.y*d3.x));
        float qy = fmaf(w1.y,d1.y, fmaf(w2.y,d2.y, w3.y*d3.y));
        A[1] = make_float2(px - qy, py + qx);
        A[6] = make_float2(px + qy, py - qx);
    }
    {   // k=2: (c2,i2)(c3,-i3)(c1,-i1)
        float px = fmaf(w2.x,s1.x, fmaf(w3.x,s2.x, fmaf(w1.x,s3.x, a0.x)));
        float py = fmaf(w2.x,s1.y, fmaf(w3.x,s2.y, fmaf(w1.x,s3.y, a0.y)));
        float qx = fmaf(w2.y,d1.x, fmaf(-w3.y,d2.x, -w1.y*d3.x));
        float qy = fmaf(w2.y,d1.y, fmaf(-w3.y,d2.y, -w1.y*d3.y));
        A[2] = make_float2(px - qy, py + qx);
        A[5] = make_float2(px + qy, py - qx);
    }
    {   // k=3: (c3,i3)(c1,-i1)(c2,i2)
        float px = fmaf(w3.x,s1.x, fmaf(w1.x,s2.x, fmaf(w2.x,s3.x, a0.x)));
        float py = fmaf(w3.x,s1.y, fmaf(w1.x,s2.y, fmaf(w2.x,s3.y, a0.y)));
        float qx = fmaf(w3.y,d1.x, fmaf(-w1.y,d2.x, w2.y*d3.x));
        float qy = fmaf(w3.y,d1.y, fmaf(-w1.y,d2.y, w2.y*d3.y));
        A[3] = make_float2(px - qy, py + qx);
        A[4] = make_float2(px + qy, py - qx);
    }

    #pragma unroll
    for (int k1 = 1; k1 < 7; k1++)
        A[k1] = cmul(A[k1], twid<INV>(gl * k1 * ST));

    #pragma unroll
    for (int m = G/2; m >= 1; m >>= 1){
        const int tstep = 224 / (2*m);
        float2 w = twid<INV>((gl & (m-1)) * tstep);
        bool up = (gl & m) != 0;
        #pragma unroll
        for (int k1 = 0; k1 < 7; k1++){
            float2 mine = A[k1];
            float2 oth;
            oth.x = __shfl_xor_sync(0xffffffffu, mine.x, m, 32);
            oth.y = __shfl_xor_sync(0xffffffffu, mine.y, m, 32);
            if (up) A[k1] = cmul(make_float2(oth.x - mine.x, oth.y - mine.y), w);
            else    A[k1] = make_float2(mine.x + oth.x, mine.y + oth.y);
        }
    }
    if (INV){
        const float s = 1.0f / (float)N;
        #pragma unroll
        for (int k1 = 0; k1 < 7; k1++){ A[k1].x *= s; A[k1].y *= s; }
    }
    #pragma unroll
    for (int k1 = 0; k1 < 7; k1++) a[k1] = A[k1];
}

__device__ __forceinline__ float blockMax448(float v){
    #pragma unroll
    for (int o = 16; o; o >>= 1) v = fmaxf(v, __shfl_xor_sync(0xffffffffu, v, o));
    __shared__ float red[14];
    int w = threadIdx.x >> 5;
    if ((threadIdx.x & 31) == 0) red[w] = v;
    __syncthreads();
    float m = -FLT_MAX;
    if (threadIdx.x == 0){
        #pragma unroll
        for (int i = 0; i < 14; i++) m = fmaxf(m, red[i]);
    }
    return m;
}

// ---- filter + twiddle + tap generation (every call) ------------------------
__device__ __forceinline__ float ffreq(int a){
    const float PI = 3.14159265358979f;
    return 2.0f*PI*(float)((a < 112) ? a : a - 224) / 224.0f;
}
__global__ void gen_filters_k(){
    int t = blockIdx.x*256 + threadIdx.x;
    const float PI = 3.14159265358979f;
    if (t < 224){
        double ang = -2.0*3.14159265358979323846*(double)t/224.0;
        g_w224[t] = make_float2((float)cos(ang), (float)sin(ang));
        return;
    }
    int u = t - 224;
    if (u < 3*8*IMG224){
        int j = u / (8*IMG224); int r = u - j*(8*IMG224);
        int l = r / IMG224;     int e = r - l*IMG224;
        int aa = e / 224, bb = e - aa*224;
        float wx = ffreq(aa), wy = ffreq(bb);
        if (j == 2){ float tmp = wx; wx = wy; wy = tmp; }   // transposed psi1
        int sj = (j == 0) ? 0 : 1;
        float th = (float)l * (PI / 8.0f);
        float xi = (3.0f*PI/4.0f) / (float)(1 << sj);
        float sg = 0.8f * (float)(1 << sj);
        float ct = cosf(th), st = sinf(th);
        float uu =  ct*wx + st*wy;
        float vv = -st*wx + ct*wy;
        float vs = vv * 2.0f;                // / slant(=0.5)
        float s2 = 0.5f*sg*sg;
        float gab = expf(-s2*((uu-xi)*(uu-xi) + vs*vs));
        float gau = expf(-s2*(uu*uu + vs*vs));
        float kap = expf(-s2*xi*xi);
        float val = gab - kap*gau;
        if (j == 0)      g_psi0 [l*IMG224 + e] = val;
        else if (j == 1) g_psi1 [l*IMG224 + e] = val;
        else             g_psi1T[l*IMG224 + e] = val;
        return;
    }
    u -= 3*8*IMG224;
    if (u < 32){
        // exact spatial taps: h[n] = (1/224) sum_k exp(-1.28 w_k^2) cos(2 pi k n / 224)
        int n, stride;
        if (u < 21){ n = u - 10; stride = 1; }              // g_h0 (224 grid)
        else       { n = u - 21 - 5; stride = 2; }          // g_h1 = h0 at even offsets
        float s = 0.f;
        for (int k = 0; k < 224; k++){
            float w = ffreq(k);
            float ang = 2.0f*PI*(float)(k*n*stride)/224.0f;
            s += expf(-1.28f*w*w) * cosf(ang);
        }
        s /= 224.0f;
        if (u < 21) g_h0[u] = s;
        else        g_h1[u-21] = s;
    }
}

// ---- @224 pass: 16 rows/block (512 thr), row FFT + coalesced transposed write
template<int MODE>
__global__ void __launch_bounds__(512) pass224_k(const float* __restrict__ xin){
    constexpr bool IN_REAL  = (MODE == 0);
    constexpr bool MUL_FILT = (MODE == 2);
    constexpr bool INV      = (MODE == 2 || MODE == 3);

    __shared__ float2 sbuf[16][225];
    int i    = blockIdx.y;
    int w    = threadIdx.x >> 5, lane = threadIdx.x & 31;
    int row  = blockIdx.x*16 + w;

    const float* inR = nullptr; const float2* inC = nullptr; const float* filt = nullptr;
    float2* outp = nullptr;
    if constexpr (MODE == 0){ inR = xin + (size_t)i*IMG224;            outp = g_s1buf; }
    if constexpr (MODE == 1){ inC = g_s1buf + (size_t)i*IMG224;        outp = g_xh;    }
    if constexpr (MODE == 2){ inC = g_xh + (size_t)(i >> 3)*IMG224;
                              filt = g_psi0 + (size_t)(i & 7)*IMG224;  outp = g_s1buf; }
    if constexpr (MODE == 3){ inC = g_s1buf + (size_t)i*IMG224;        outp = g_s2buf; }
    if constexpr (MODE == 4){ inC = g_s2buf + (size_t)i*IMG224;        outp = g_u1h2;  }

    float2 a[7];
    #pragma unroll
    for (int n1 = 0; n1 < 7; n1++){
        int idx = row*224 + n1*32 + lane;
        float2 v;
        if constexpr (IN_REAL) v = make_float2(inR[idx], 0.f);
        else                   v = inC[idx];
        if constexpr (MUL_FILT){ float f = filt[idx]; v.x *= f; v.y *= f; }
        a[n1] = v;
    }
    fft_regs<5, INV>(a, lane);

    if constexpr (MODE == 3){
        // modulus (ifft2 complete) -> save spatial u1 -> forward FFT
        float* rb = (float*)&sbuf[w][0];
        int k2m = __brev((unsigned)lane) >> 27;
        #pragma unroll
        for (int k1 = 0; k1 < 7; k1++)
            rb[k1 + 7*k2m] = sqrtf(a[k1].x*a[k1].x + a[k1].y*a[k1].y);
        __syncwarp();
        float* u1o = g_u1 + (size_t)i*IMG224 + row*224;
        #pragma unroll
        for (int n1 = 0; n1 < 7; n1++){
            float v = rb[n1*32 + lane];
            u1o[n1*32 + lane] = v;
            a[n1] = make_float2(v, 0.f);
        }
        __syncwarp();
        fft_regs<5, false>(a, lane);
    }

    int k2 = __brev((unsigned)lane) >> 27;
    #pragma unroll
    for (int k1 = 0; k1 < 7; k1++) sbuf[w][k1 + 7*k2] = a[k1];
    __syncthreads();

    int rr   = threadIdx.x & 15;
    int kk   = threadIdx.x >> 4;
    int grow = blockIdx.x*16 + rr;
    float2* o = outp + (size_t)i*IMG224;
    #pragma unroll
    for (int it = 0; it < 7; it++){
        int k = kk + it*32;
        o[k*224 + grow] = sbuf[rr][k];
    }
}

// ---- pre-fold kernel: reads each source ONCE, emits all 8 l2 folds ---------
__global__ void __launch_bounds__(512) fold2_k(){
    int s = blockIdx.y;
    const float2* src; const float* filt; int outBase;
    if (s < 48){ src = g_xh  + (size_t)s*IMG224;       filt = g_psi1;  outBase = s*8; }
    else       { src = g_u1h2 + (size_t)(s-48)*IMG224; filt = g_psi1T; outBase = 384 + (s-48)*8; }

    int base = blockIdx.x*1792;
    for (int e = base + threadIdx.x; e < base + 1792; e += 512){
        int aa = e/112, bb = e - aa*112;
        int i00 =  aa      *224 + bb, i01 =  aa      *224 + bb + 112;
        int i10 = (aa+112) *224 + bb, i11 = (aa+112) *224 + bb + 112;
        float2 s00 = src[i00], s01 = src[i01], s10 = src[i10], s11 = src[i11];
        #pragma unroll
        for (int l2 = 0; l2 < 8; l2++){
            const float* f = filt + (size_t)l2*IMG224;
            float f00 = f[i00], f01 = f[i01], f10 = f[i10], f11 = f[i11];
            float2 acc;
            acc.x = fmaf(s00.x,f00, fmaf(s01.x,f01, fmaf(s10.x,f10, s11.x*f11)));
            acc.y = fmaf(s00.y,f00, fmaf(s01.y,f01, fmaf(s10.y,f10, s11.y*f11)));
            g_fold[(size_t)(outBase + l2)*IMG112 + e] = make_float2(acc.x*0.25f, acc.y*0.25f);
        }
    }
}

// ---- fused @112 chain: ifft2 -> |.| -> separable blur (stride 2) -> max ----
__device__ __forceinline__ void chain112(const float2* __restrict__ fsrc,
                                         float* featOut){
    extern __shared__ float2 sm[];
    float2* img = sm;                   // 112 x 113 complex
    float*  smf = (float*)sm;           // float view
    __shared__ float sh_h[11];
    int tid = threadIdx.x;
    if (tid < 11) sh_h[tid] = g_h1[tid];
    int gl = tid & 15, grp = tid >> 4;  // 28 groups of 16

    // ifft2 row pass, loading straight from global
    for (int r = grp; r < 112; r += 28){
        float2 a[7];
        #pragma unroll
        for (int n1 = 0; n1 < 7; n1++) a[n1] = fsrc[r*112 + n1*16 + gl];
        fft_regs<4, true>(a, gl);
        int k2 = __brev((unsigned)gl) >> 28;
        #pragma unroll
        for (int k1 = 0; k1 < 7; k1++) img[r*113 + k1 + 7*k2] = a[k1];
    }
    __syncthreads();
    // ifft2 col pass, modulus stored into .x slots
    for (int c = grp; c < 112; c += 28){
        float2 a[7];
        #pragma unroll
        for (int n1 = 0; n1 < 7; n1++) a[n1] = img[(n1*16 + gl)*113 + c];
        fft_regs<4, true>(a, gl);
        int k2 = __brev((unsigned)gl) >> 28;
        #pragma unroll
        for (int k1 = 0; k1 < 7; k1++){
            float2 z = a[k1];
            smf[((k1 + 7*k2)*113 + c)*2] = sqrtf(z.x*z.x + z.y*z.y);
        }
    }
    __syncthreads();

    // horizontal blur at stride-2 output columns: hb[r][c] (112 x 56)
    float rh[14];
    #pragma unroll
    for (int it = 0; it < 14; it++){
        int e = tid + it*448;
        int r = e % 112, c = e / 112;
        float acc = 0.f;
        #pragma unroll
        for (int d = 0; d < 11; d++){
            int cc = 2*c + d - 5;
            if (cc < 0) cc += 112; else if (cc >= 112) cc -= 112;
            acc = fmaf(sh_h[d], smf[(r*113 + cc)*2], acc);
        }
        rh[it] = acc;
    }
    __syncthreads();
    #pragma unroll
    for (int it = 0; it < 14; it++){
        int e = tid + it*448;
        int r = e % 112, c = e / 112;
        smf[r*57 + c] = rh[it];          // hb overlay, pitch 57 (conflict-free)
    }
    __syncthreads();

    // vertical blur at stride-2 output rows + max
    float mx = -FLT_MAX;
    #pragma unroll
    for (int it = 0; it < 7; it++){
        int e = tid + it*448;
        int a = e / 56, b = e % 56;
        float acc = 0.f;
        #pragma unroll
        for (int d = 0; d < 11; d++){
            int rr = 2*a + d - 5;
            if (rr < 0) rr += 112; else if (rr >= 112) rr -= 112;
            acc = fmaf(sh_h[d], smf[rr*57 + b], acc);
        }
        mx = fmaxf(mx, acc);
    }
    float m = blockMax448(mx);
    if (tid == 0) *featOut = m;
}

// merged j1=1 first order + second order (3456 blocks)
__global__ void __launch_bounds__(448, 2) scatter2_k(){
    int i = blockIdx.x;
    int featIdx;
    if (i < 384){
        int bc = i >> 3, l = i & 7;
        featIdx = bc*81 + 9 + l;
    } else {
        int v = i - 384;
        int bc = v >> 6, l1 = (v >> 3) & 7, l2 = v & 7;
        featIdx = bc*81 + 17 + l1*8 + l2;
    }
    chain112(g_fold + (size_t)i*IMG112, &g_feat[featIdx]);
}

// ---- s0 / s1(j1=0): spatial blur @224, stride 4, circular, + max -----------
__global__ void __launch_bounds__(448) blur224_k(const float* __restrict__ x){
    __shared__ float hb[224*57];        // 51KB
    __shared__ float sh_h[21];
    int i = blockIdx.x;                 // [0,48): s0 from x ; [48,432): s1 j1=0 from u1
    const float* src; int featIdx;
    if (i < 48){ src = x + (size_t)i*IMG224; featIdx = i*81; }
    else {
        int j = i - 48;
        src = g_u1 + (size_t)j*IMG224;
        featIdx = (j >> 3)*81 + 1 + (j & 7);
    }
    int tid = threadIdx.x;
    if (tid < 21) sh_h[tid] = g_h0[tid];
    __syncthreads();

    int rr = tid / 56, c = tid % 56;    // 8 rows x 56 cols per sweep
    for (int r0 = 0; r0 < 224; r0 += 8){
        int r = r0 + rr;
        float acc = 0.f;
        #pragma unroll
        for (int d = 0; d < 21; d++){
            int cc = 4*c + d - 10;
            if (cc < 0) cc += 224; else if (cc >= 224) cc -= 224;
            acc = fmaf(sh_h[d], __ldg(src + r*224 + cc), acc);
        }
        hb[r*57 + c] = acc;
    }
    __syncthreads();

    float mx = -FLT_MAX;
    #pragma unroll
    for (int it = 0; it < 7; it++){
        int e = tid + it*448;
        int a = e / 56, b = e % 56;
        float acc = 0.f;
        #pragma unroll
        for (int d = 0; d < 21; d++){
            int r2 = 4*a + d - 10;
            if (r2 < 0) r2 += 224; else if (r2 >= 224) r2 -= 224;
            acc = fmaf(sh_h[d], hb[r2*57 + b], acc);
        }
        mx = fmaxf(mx, acc);
    }
    float m = blockMax448(mx);
    if (tid == 0) g_feat[featIdx] = m;
}

// ---- final linear ----------------------------------------------------------
__global__ void linear_k(const float* __restrict__ W, const float* __restrict__ bias,
                         float* __restrict__ out){
    __shared__ float gs[243];
    int b = blockIdx.x;
    for (int k = threadIdx.x; k < 243; k += 256) gs[k] = g_feat[b*243 + k];
    __syncthreads();
    for (int o = threadIdx.x; o < 1000; o += 256){
        float acc = bias[o];
        const float* wr = W + o*243;
        #pragma unroll 3
        for (int k = 0; k < 243; k++) acc = fmaf(gs[k], wr[k], acc);
        out[b*1000 + o] = acc;
    }
}

// ---------------------------------------------------------------------------
extern "C" void kernel_launch(void* const* d_in, const int* in_sizes, int n_in,
                              void* d_out, int out_size){
    const float *x = nullptr, *W = nullptr, *bias = nullptr;
    for (int i = 0; i < n_in; i++){
        if      (in_sizes[i] == 16*3*224*224) x    = (const float*)d_in[i];
        else if (in_sizes[i] == 1000*243)     W    = (const float*)d_in[i];
        else if (in_sizes[i] == 1000)         bias = (const float*)d_in[i];
    }
    float* out = (float*)d_out;

    const int SM_CHAIN = 112*113*(int)sizeof(float2);  // 101,248 B
    cudaFuncSetAttribute(scatter2_k, cudaFuncAttributeMaxDynamicSharedMemorySize, SM_CHAIN);

    int genTotal = 224 + 3*8*IMG224 + 32;
    gen_filters_k<<<(genTotal + 255)/256, 256>>>();

    pass224_k<0><<<dim3(14, 48),  512>>>(x);        // x -> s1buf (rows fwd)
    pass224_k<1><<<dim3(14, 48),  512>>>(nullptr);  // s1buf -> xh
    pass224_k<2><<<dim3(14, 384), 512>>>(nullptr);  // xh*psi0 -> s1buf (inv)
    pass224_k<3><<<dim3(14, 384), 512>>>(nullptr);  // inv + |.| -> u1, fwd -> s2buf
    pass224_k<4><<<dim3(14, 384), 512>>>(nullptr);  // s2buf -> u1h2 (transposed)

    fold2_k<<<dim3(7, 432), 512>>>();               // prefold all 3456 chain inputs
    blur224_k<<<432, 448>>>(x);                     // s0 + s1(j1=0) via spatial blur
    scatter2_k<<<3456, 448, SM_CHAIN>>>();          // s1(j1=1) + s2
    linear_k<<<16, 256>>>(W, bias, out);
    (void)out_size;
}